// round 8
// baseline (speedup 1.0000x reference)
#include <cuda_runtime.h>
#include <math.h>
#include <stdint.h>

#define T_TOK 2048
#define HIDDEN 5120
#define NH 32
#define DQ 128
#define DR 64
#define DV 128
#define QLORA 1536
#define KVLORA 512
#define KV_W (KVLORA + DR)        // 576
#define QDIM (DQ + DR)            // 192
#define KVUPW (NH * (DQ + DV))    // 8192
#define QW (NH * QDIM)            // 6144
#define ATTNW (NH * DV)           // 4096

// ---------------- scratch (device globals; no runtime allocation) ----------
__device__ float g_qa[T_TOK * QLORA];
__device__ float g_kv[T_TOK * KV_W];
__device__ float g_q[T_TOK * QW];
__device__ float g_kvup[T_TOK * KVUPW];
__device__ float g_kpe[T_TOK * DR];
__device__ float g_attn[T_TOK * ATTNW];
__device__ float g_hid_t[T_TOK * HIDDEN];   // tf32-rounded hidden (A of 2 GEMMs)

// ======================= helpers ===========================================
__device__ __forceinline__ uint32_t smem_u32(const void* p) {
    uint32_t a;
    asm("{ .reg .u64 t; cvta.to.shared.u64 t, %1; cvt.u32.u64 %0, t; }"
        : "=r"(a) : "l"(p));
    return a;
}

__device__ __forceinline__ float tf32r(float x) {
    uint32_t u;
    asm("cvt.rna.tf32.f32 %0, %1;" : "=r"(u) : "f"(x));
    return __uint_as_float(u);
}

__device__ __forceinline__ float ex2f(float x) {
    float y;
    asm("ex2.approx.ftz.f32 %0, %1;" : "=f"(y) : "f"(x));
    return y;
}

__device__ __forceinline__ void mma_tf32(float c[4], const uint32_t a[4],
                                         uint32_t b0, uint32_t b1) {
    asm volatile(
        "mma.sync.aligned.m16n8k8.row.col.f32.tf32.tf32.f32 "
        "{%0,%1,%2,%3}, {%4,%5,%6,%7}, {%8,%9}, {%0,%1,%2,%3};"
        : "+f"(c[0]), "+f"(c[1]), "+f"(c[2]), "+f"(c[3])
        : "r"(a[0]), "r"(a[1]), "r"(a[2]), "r"(a[3]), "r"(b0), "r"(b1));
}

// ---------------- tf32 pre-round pass (hidden only) ------------------------
__global__ void round_tf32_kernel(const float* __restrict__ in,
                                  float* __restrict__ o, int n4) {
    for (int i = blockIdx.x * 256 + threadIdx.x; i < n4; i += gridDim.x * 256) {
        float4 v = ((const float4*)in)[i];
        v.x = tf32r(v.x); v.y = tf32r(v.y); v.z = tf32r(v.z); v.w = tf32r(v.w);
        ((float4*)o)[i] = v;
    }
}

// ---------------- RoPE angle ------------------------------------------------
// a_i = pos * 10000^(-(i&31)/32) = pos * exp2(-(i&31) * log2(10000)/32)
#define L2T_32 0.41524101186091903f   // log2(10000)/32
__device__ __forceinline__ float rope_angle(float fpos, int i) {
    return fpos * ex2f(-(float)(i & 31) * L2T_32);
}
// NOTE: epilogue uses accurate exp2f for the frequency (matches powf path).
__device__ __forceinline__ float rope_freq(int i) {
    return exp2f(-(float)(i & 31) * L2T_32);
}

// ======================= tf32 mma.sync GEMM ================================
// C[M,N] = A[M,K] @ B[K,N]; A PRE-ROUNDED tf32 in gmem, B raw fp32 (cvt on
// fragment load). M mult of 128, K mult of 32.
// CTA 128x128, BK=32, 256 threads (8 warps 4x2, warp tile 32x64).
// mode: 0 = plain; 1 = q-RoPE (rotate cols with (col%192)>=128, per-head);
//       2 = kv split (cols>=512 rotated -> kpe, not written to C).
#define GSTAGE 32768
#define GSMEM (2 * GSTAGE)

__device__ __forceinline__ void g_load_stage(uint32_t sbase, int s,
        const float* __restrict__ A, int lda,
        const float* __restrict__ B, int ldb,
        int brow, int bcol, int N, int k0, int tid) {
    const uint32_t sA = sbase + s * GSTAGE;
    const uint32_t sB = sA + 16384;
#pragma unroll
    for (int it = 0; it < 4; it++) {
        const int f4 = it * 256 + tid;
        const int r = f4 >> 3, c16 = f4 & 7;
        const uint32_t dst = sA + r * 128 + ((c16 ^ (r & 7)) << 4);
        const float* src = A + (size_t)(brow + r) * lda + k0 + c16 * 4;
        asm volatile("cp.async.ca.shared.global [%0], [%1], 16;"
                     :: "r"(dst), "l"(src) : "memory");
    }
#pragma unroll
    for (int it = 0; it < 4; it++) {
        const int f4 = it * 256 + tid;
        const int k = f4 >> 5, c16 = f4 & 31;
        const uint32_t dst = sB + k * 512 + ((c16 ^ ((k & 3) << 1)) << 4);
        const float* src = B + (size_t)(k0 + k) * ldb + bcol + c16 * 4;
        const int sz = (bcol + c16 * 4 + 4 <= N) ? 16 : 0;
        asm volatile("cp.async.ca.shared.global [%0], [%1], 16, %2;"
                     :: "r"(dst), "l"(src), "r"(sz) : "memory");
    }
    asm volatile("cp.async.commit_group;" ::: "memory");
}

__global__ __launch_bounds__(256, 2) void sgemm_mma(
        const float* __restrict__ A, int lda,
        const float* __restrict__ B, int ldb,
        float* __restrict__ C, int ldc, int N, int K,
        float oscale, int rnd, int mode,
        const int* __restrict__ pos, float* __restrict__ kpe) {
    extern __shared__ char sm[];
    const uint32_t sbase = smem_u32(sm);
    const int tid = threadIdx.x;
    const int lane = tid & 31;
    const int wid = tid >> 5;
    const int wm = wid >> 1, wn = wid & 1;
    const int brow = blockIdx.y * 128;
    const int bcol = blockIdx.x * 128;

    float acc[2][8][4];
#pragma unroll
    for (int mi = 0; mi < 2; mi++)
#pragma unroll
        for (int ni = 0; ni < 8; ni++)
#pragma unroll
            for (int j = 0; j < 4; j++) acc[mi][ni][j] = 0.f;

    const int nch = K / 32;
    g_load_stage(sbase, 0, A, lda, B, ldb, brow, bcol, N, 0, tid);

    for (int i = 0; i < nch; i++) {
        const int s = i & 1;
        if (i + 1 < nch) {
            g_load_stage(sbase, s ^ 1, A, lda, B, ldb, brow, bcol, N,
                         (i + 1) * 32, tid);
            asm volatile("cp.async.wait_group 1;" ::: "memory");
        } else {
            asm volatile("cp.async.wait_group 0;" ::: "memory");
        }
        __syncthreads();

        const float* sA = (const float*)(sm + s * GSTAGE);
        const float* sB = (const float*)(sm + s * GSTAGE + 16384);

#pragma unroll
        for (int ks = 0; ks < 4; ks++) {
            uint32_t a[2][4];
            const int q = lane >> 2, rlo = lane & 3;
            const int c0 = ks * 8 + rlo;
#pragma unroll
            for (int mi = 0; mi < 2; mi++) {
                const int r0 = wm * 32 + mi * 16 + q;
                const int r1 = r0 + 8;
                a[mi][0] = __float_as_uint(sA[r0 * 32 + ((((c0 >> 2) ^ (r0 & 7))) << 2) + rlo]);
                a[mi][1] = __float_as_uint(sA[r1 * 32 + ((((c0 >> 2) ^ (r1 & 7))) << 2) + rlo]);
                a[mi][2] = __float_as_uint(sA[r0 * 32 + (((((c0 + 4) >> 2) ^ (r0 & 7))) << 2) + rlo]);
                a[mi][3] = __float_as_uint(sA[r1 * 32 + (((((c0 + 4) >> 2) ^ (r1 & 7))) << 2) + rlo]);
            }
            uint32_t b[8][2];
            const int kb0 = ks * 8 + rlo, kb1 = kb0 + 4;
#pragma unroll
            for (int ni = 0; ni < 8; ni++) {
                const int n = wn * 64 + ni * 8 + q;
                // B raw fp32 in smem -> tf32-round at fragment load (RNA)
                b[ni][0] = __float_as_uint(tf32r(sB[kb0 * 128 + (((n >> 2) ^ ((kb0 & 3) << 1)) << 2) + (n & 3)]));
                b[ni][1] = __float_as_uint(tf32r(sB[kb1 * 128 + (((n >> 2) ^ ((kb1 & 3) << 1)) << 2) + (n & 3)]));
            }
#pragma unroll
            for (int mi = 0; mi < 2; mi++)
#pragma unroll
                for (int ni = 0; ni < 8; ni++)
                    mma_tf32(acc[mi][ni], a[mi], b[ni][0], b[ni][1]);
        }
        __syncthreads();
    }

    // ---- epilogue: oscale, optional RoPE, optional tf32 round, store ----
    const int q = lane >> 2, rlo = lane & 3;
#pragma unroll
    for (int mi = 0; mi < 2; mi++) {
        const int r0 = brow + wm * 32 + mi * 16 + q;
        const int r1 = r0 + 8;
        float fp0 = 0.f, fp1 = 0.f;
        if (mode != 0) { fp0 = (float)pos[r0]; fp1 = (float)pos[r1]; }
#pragma unroll
        for (int ni = 0; ni < 8; ni++) {
            const int col = bcol + wn * 64 + ni * 8 + rlo * 2;
            if (col >= N) continue;
            float x0 = acc[mi][ni][0] * oscale, x1 = acc[mi][ni][1] * oscale;
            float x2 = acc[mi][ni][2] * oscale, x3 = acc[mi][ni][3] * oscale;

            if (mode == 1) {
                const int d = col % QDIM;
                if (d >= DQ) {
                    const int i0 = d - DQ;             // even
                    const float f0 = rope_freq(i0), f1 = rope_freq(i0 + 1);
                    float s0, c0, s1, c1;
                    sincosf(fp0 * f0, &s0, &c0);
                    sincosf(fp0 * f1, &s1, &c1);
                    float nx0 = x0 * c0 - x1 * s0;
                    float nx1 = x1 * c1 + x0 * s1;
                    x0 = nx0; x1 = nx1;
                    sincosf(fp1 * f0, &s0, &c0);
                    sincosf(fp1 * f1, &s1, &c1);
                    float nx2 = x2 * c0 - x3 * s0;
                    float nx3 = x3 * c1 + x2 * s1;
                    x2 = nx2; x3 = nx3;
                }
            } else if (mode == 2 && col >= KVLORA) {
                const int i0 = col - KVLORA;           // even, [0,64)
                const float f0 = rope_freq(i0), f1 = rope_freq(i0 + 1);
                float s0, c0, s1, c1;
                sincosf(fp0 * f0, &s0, &c0);
                sincosf(fp0 * f1, &s1, &c1);
                *(float2*)&kpe[(size_t)r0 * DR + i0] =
                    make_float2(tf32r(x0 * c0 - x1 * s0), tf32r(x1 * c1 + x0 * s1));
                sincosf(fp1 * f0, &s0, &c0);
                sincosf(fp1 * f1, &s1, &c1);
                *(float2*)&kpe[(size_t)r1 * DR + i0] =
                    make_float2(tf32r(x2 * c0 - x3 * s0), tf32r(x3 * c1 + x2 * s1));
                continue;  // pe cols not written to C
            }

            if (rnd) {
                x0 = tf32r(x0); x1 = tf32r(x1); x2 = tf32r(x2); x3 = tf32r(x3);
            }
            *(float2*)&C[(size_t)r0 * ldc + col] = make_float2(x0, x1);
            *(float2*)&C[(size_t)r1 * ldc + col] = make_float2(x2, x3);
        }
    }
}

// ---------------- RMSNorm in place (writes tf32-rounded) --------------------
__global__ void rmsnorm_kernel(float* __restrict__ x, const float* __restrict__ g,
                               int width, int stride) {
    const int row = blockIdx.x;
    float* p = x + (size_t)row * stride;
    const int tid = threadIdx.x;
    float s = 0.f;
    for (int i = tid; i < width; i += 256) {
        float v = p[i];
        s += v * v;
    }
    __shared__ float red[256];
    red[tid] = s;
    __syncthreads();
    for (int o = 128; o > 0; o >>= 1) {
        if (tid < o) red[tid] += red[tid + o];
        __syncthreads();
    }
    const float inv = rsqrtf(red[0] / (float)width + 1e-6f);
    for (int i = tid; i < width; i += 256) p[i] = tf32r(p[i] * inv * g[i]);
}

// ================ flash attention, tf32 mma, log2-domain softmax ===========
// grid (16, 32): 128 q rows per CTA, 8 warps (16 rows each), k-tiles of 64.
// Q pre-scaled by (DQ+DR)^-0.5 * log2(e): S is in log2 units -> ex2 direct.
#define FQP 196
#define FKP 196
#define FVP 136
#define FPP 72
#define FLASH_SMEM ((128 * FQP + 64 * FKP + 64 * FVP + 128 * FPP) * 4)  // 222208

__global__ __launch_bounds__(256, 1) void flash_tc(
        const float* __restrict__ q, const float* __restrict__ kvup,
        const float* __restrict__ kpe, float* __restrict__ out) {
    const int ib = blockIdx.x;
    const int h = blockIdx.y;
    const int tid = threadIdx.x;
    const int lane = tid & 31;
    const int wid = tid >> 5;

    extern __shared__ float fs[];
    float* sQ = fs;
    float* sK = sQ + 128 * FQP;
    float* sV = sK + 64 * FKP;
    float* sP = sV + 64 * FVP;

    for (int idx = tid; idx < 128 * 48; idx += 256) {
        const int r = idx / 48, d4 = idx % 48;
        *(float4*)&sQ[r * FQP + d4 * 4] =
            *(const float4*)&q[(size_t)(ib * 128 + r) * QW + h * QDIM + d4 * 4];
    }

    const int r = lane >> 2, c2 = lane & 3;
    const int qr0 = ib * 128 + wid * 16 + r;
    float m0 = -INFINITY, m1 = -INFINITY, l0 = 0.f, l1 = 0.f;
    float O[16][4];
#pragma unroll
    for (int nt = 0; nt < 16; nt++)
#pragma unroll
        for (int j = 0; j < 4; j++) O[nt][j] = 0.f;

    const int njb = 2 * ib + 2;
    for (int jb = 0; jb < njb; jb++) {
        __syncthreads();
        for (int idx = tid; idx < 64 * 48; idx += 256) {
            const int rr = idx / 48, d4 = idx % 48;
            const int kt = jb * 64 + rr;
            float4 v;
            if (d4 < 32) v = *(const float4*)&kvup[(size_t)kt * KVUPW + h * 256 + d4 * 4];
            else         v = *(const float4*)&kpe[(size_t)kt * DR + (d4 - 32) * 4];
            *(float4*)&sK[rr * FKP + d4 * 4] = v;
        }
        for (int idx = tid; idx < 64 * 32; idx += 256) {
            const int rr = idx >> 5, d4 = idx & 31;
            *(float4*)&sV[rr * FVP + d4 * 4] =
                *(const float4*)&kvup[(size_t)(jb * 64 + rr) * KVUPW + h * 256 + 128 + d4 * 4];
        }
        __syncthreads();

        float S[8][4];
#pragma unroll
        for (int nt = 0; nt < 8; nt++)
#pragma unroll
            for (int j = 0; j < 4; j++) S[nt][j] = 0.f;

#pragma unroll
        for (int ks = 0; ks < 24; ks++) {
            uint32_t a[4];
            const int base = (wid * 16 + r) * FQP + ks * 8 + c2;
            a[0] = __float_as_uint(sQ[base]);
            a[1] = __float_as_uint(sQ[base + 8 * FQP]);
            a[2] = __float_as_uint(sQ[base + 4]);
            a[3] = __float_as_uint(sQ[base + 8 * FQP + 4]);
#pragma unroll
            for (int nt = 0; nt < 8; nt++) {
                const int kb = (nt * 8 + r) * FKP + ks * 8 + c2;
                mma_tf32(S[nt], a, __float_as_uint(sK[kb]),
                         __float_as_uint(sK[kb + 4]));
            }
        }

        if (jb >= 2 * ib) {
#pragma unroll
            for (int nt = 0; nt < 8; nt++) {
                const int kc = jb * 64 + nt * 8 + c2 * 2;
                if (kc > qr0)     S[nt][0] = -1e30f;
                if (kc + 1 > qr0) S[nt][1] = -1e30f;
                if (kc > qr0 + 8)     S[nt][2] = -1e30f;
                if (kc + 1 > qr0 + 8) S[nt][3] = -1e30f;
            }
        }

        float mx0 = -INFINITY, mx1 = -INFINITY;
#pragma unroll
        for (int nt = 0; nt < 8; nt++) {
            mx0 = fmaxf(mx0, fmaxf(S[nt][0], S[nt][1]));
            mx1 = fmaxf(mx1, fmaxf(S[nt][2], S[nt][3]));
        }
        mx0 = fmaxf(mx0, __shfl_xor_sync(0xffffffffu, mx0, 1));
        mx0 = fmaxf(mx0, __shfl_xor_sync(0xffffffffu, mx0, 2));
        mx1 = fmaxf(mx1, __shfl_xor_sync(0xffffffffu, mx1, 1));
        mx1 = fmaxf(mx1, __shfl_xor_sync(0xffffffffu, mx1, 2));
        const float mn0 = fmaxf(m0, mx0), mn1 = fmaxf(m1, mx1);
        const float al0 = ex2f(m0 - mn0), al1 = ex2f(m1 - mn1);
        m0 = mn0; m1 = mn1;
        float rs0 = 0.f, rs1 = 0.f;
#pragma unroll
        for (int nt = 0; nt < 8; nt++) {
            const float p0 = ex2f(S[nt][0] - mn0);
            const float p1 = ex2f(S[nt][1] - mn0);
            const float p2 = ex2f(S[nt][2] - mn1);
            const float p3 = ex2f(S[nt][3] - mn1);
            rs0 += p0 + p1;
            rs1 += p2 + p3;
            const int pr = (wid * 16 + r) * FPP + nt * 8 + c2 * 2;
            *(float2*)&sP[pr] = make_float2(tf32r(p0), tf32r(p1));
            *(float2*)&sP[pr + 8 * FPP] = make_float2(tf32r(p2), tf32r(p3));
        }
        rs0 += __shfl_xor_sync(0xffffffffu, rs0, 1);
        rs0 += __shfl_xor_sync(0xffffffffu, rs0, 2);
        rs1 += __shfl_xor_sync(0xffffffffu, rs1, 1);
        rs1 += __shfl_xor_sync(0xffffffffu, rs1, 2);
        l0 = l0 * al0 + rs0;
        l1 = l1 * al1 + rs1;
#pragma unroll
        for (int nt = 0; nt < 16; nt++) {
            O[nt][0] *= al0; O[nt][1] *= al0;
            O[nt][2] *= al1; O[nt][3] *= al1;
        }
        __syncwarp();

#pragma unroll
        for (int kf = 0; kf < 8; kf++) {
            uint32_t a[4];
            const int pb = (wid * 16 + r) * FPP + kf * 8 + c2;
            a[0] = __float_as_uint(sP[pb]);
            a[1] = __float_as_uint(sP[pb + 8 * FPP]);
            a[2] = __float_as_uint(sP[pb + 4]);
            a[3] = __float_as_uint(sP[pb + 8 * FPP + 4]);
#pragma unroll
            for (int nt = 0; nt < 16; nt++) {
                const int vb = (kf * 8 + c2) * FVP + nt * 8 + r;
                mma_tf32(O[nt], a, __float_as_uint(sV[vb]),
                         __float_as_uint(sV[vb + 4 * FVP]));
            }
        }
    }

    const float inv0 = 1.f / l0, inv1 = 1.f / l1;
    const int row0 = ib * 128 + wid * 16 + r;
#pragma unroll
    for (int nt = 0; nt < 16; nt++) {
        const int col = h * DV + nt * 8 + c2 * 2;
        *(float2*)&out[(size_t)row0 * ATTNW + col] =
            make_float2(tf32r(O[nt][0] * inv0), tf32r(O[nt][1] * inv0));
        *(float2*)&out[(size_t)(row0 + 8) * ATTNW + col] =
            make_float2(tf32r(O[nt][2] * inv1), tf32r(O[nt][3] * inv1));
    }
}

// ---------------- launch -----------------------------------------------------
extern "C" void kernel_launch(void* const* d_in, const int* in_sizes, int n_in,
                              void* d_out, int out_size) {
    const int* positions = (const int*)d_in[0];
    const float* hidden = (const float*)d_in[1];
    const float* w_qa = (const float*)d_in[2];
    const float* gamma_q = (const float*)d_in[3];
    const float* w_qb = (const float*)d_in[4];
    const float* w_kva = (const float*)d_in[5];
    const float* gamma_kv = (const float*)d_in[6];
    const float* w_kvb = (const float*)d_in[7];
    const float* w_o = (const float*)d_in[8];
    float* out = (float*)d_out;

    float *qa, *kv, *q, *kvup, *kpe, *attn, *hid_t;
    cudaGetSymbolAddress((void**)&qa, g_qa);
    cudaGetSymbolAddress((void**)&kv, g_kv);
    cudaGetSymbolAddress((void**)&q, g_q);
    cudaGetSymbolAddress((void**)&kvup, g_kvup);
    cudaGetSymbolAddress((void**)&kpe, g_kpe);
    cudaGetSymbolAddress((void**)&attn, g_attn);
    cudaGetSymbolAddress((void**)&hid_t, g_hid_t);

    cudaFuncSetAttribute(sgemm_mma, cudaFuncAttributeMaxDynamicSharedMemorySize, GSMEM);
    cudaFuncSetAttribute(flash_tc, cudaFuncAttributeMaxDynamicSharedMemorySize,
                         FLASH_SMEM);

    // (DQ+DR)^-0.5 * log2(e): softmax runs in log2 domain
    const float SCALE_L2E = 0.07216878364870323f * 1.4426950408889634f;
    const int MB = T_TOK / 128;  // 16

    // 1: pre-round hidden to tf32 (A of the two down-proj GEMMs)
    round_tf32_kernel<<<2048, 256>>>(hidden, hid_t, T_TOK * HIDDEN / 4);
    // 2: q_a = hid @ w_qa           [2048,1536]
    sgemm_mma<<<dim3(QLORA / 128, MB), 256, GSMEM>>>(
        hid_t, HIDDEN, w_qa, QLORA, qa, QLORA, QLORA, HIDDEN, 1.f, 0, 0,
        positions, kpe);
    // 3: kv = hid @ w_kva           [2048,576]; cols>=512 roped -> kpe
    sgemm_mma<<<dim3((KV_W + 127) / 128, MB), 256, GSMEM>>>(
        hid_t, HIDDEN, w_kva, KV_W, kv, KV_W, KV_W, HIDDEN, 1.f, 0, 2,
        positions, kpe);
    // 4,5: rmsnorm (writes tf32)
    rmsnorm_kernel<<<T_TOK, 256>>>(qa, gamma_q, QLORA, QLORA);
    rmsnorm_kernel<<<T_TOK, 256>>>(kv, gamma_kv, KVLORA, KV_W);
    // 6: q = (q_c @ w_qb) * scale*log2e, q-RoPE fused, tf32   [2048,6144]
    sgemm_mma<<<dim3(QW / 128, MB), 256, GSMEM>>>(
        qa, QLORA, w_qb, QW, q, QW, QW, QLORA, SCALE_L2E, 1, 1,
        positions, kpe);
    // 7: kv_up = kv_c @ w_kvb, tf32 [2048,8192]
    sgemm_mma<<<dim3(KVUPW / 128, MB), 256, GSMEM>>>(
        kv, KV_W, w_kvb, KVUPW, kvup, KVUPW, KVUPW, KVLORA, 1.f, 1, 0,
        positions, kpe);
    // 8: attention (tensor-core, log2-domain softmax)
    flash_tc<<<dim3(T_TOK / 128, NH), 256, FLASH_SMEM>>>(q, kvup, kpe, attn);
    // 9: out = attn @ w_o           [2048,5120]
    sgemm_mma<<<dim3(HIDDEN / 128, MB), 256, GSMEM>>>(
        attn, ATTNW, w_o, HIDDEN, out, HIDDEN, HIDDEN, ATTNW, 1.f, 0, 0,
        positions, kpe);
}

// round 10
// speedup vs baseline: 1.1553x; 1.1553x over previous
#include <cuda_runtime.h>
#include <math.h>
#include <stdint.h>

#define T_TOK 2048
#define HIDDEN 5120
#define NH 32
#define DQ 128
#define DR 64
#define DV 128
#define QLORA 1536
#define KVLORA 512
#define KV_W (KVLORA + DR)        // 576
#define QDIM (DQ + DR)            // 192
#define KVUPW (NH * (DQ + DV))    // 8192
#define QW (NH * QDIM)            // 6144
#define ATTNW (NH * DV)           // 4096
#define CMBW (QLORA + KV_W)       // 2112 combined down-proj width

// ---------------- scratch (device globals; no runtime allocation) ----------
__device__ float g_cmb[T_TOK * CMBW];       // q_a | kv_c (rmsnormed in place)
__device__ float g_q[T_TOK * QW];
__device__ float g_kvup[T_TOK * KVUPW];
__device__ float g_kpe[T_TOK * DR];
__device__ float g_attn[T_TOK * ATTNW];
__device__ float g_hid_t[T_TOK * HIDDEN];   // tf32 hidden
__device__ float g_wcmb_t[HIDDEN * CMBW];   // tf32 [w_qa | w_kva]
__device__ float g_wqb_t[QLORA * QW];
__device__ float g_wkvb_t[KVLORA * KVUPW];
__device__ float g_wo_t[ATTNW * HIDDEN];

// ======================= helpers ===========================================
__device__ __forceinline__ uint32_t smem_u32(const void* p) {
    uint32_t a;
    asm("{ .reg .u64 t; cvta.to.shared.u64 t, %1; cvt.u32.u64 %0, t; }"
        : "=r"(a) : "l"(p));
    return a;
}

__device__ __forceinline__ float tf32r(float x) {
    uint32_t u;
    asm("cvt.rna.tf32.f32 %0, %1;" : "=r"(u) : "f"(x));
    return __uint_as_float(u);
}

__device__ __forceinline__ float ex2f(float x) {
    float y;
    asm("ex2.approx.ftz.f32 %0, %1;" : "=f"(y) : "f"(x));
    return y;
}

__device__ __forceinline__ void mma_tf32(float c[4], const uint32_t a[4],
                                         uint32_t b0, uint32_t b1) {
    asm volatile(
        "mma.sync.aligned.m16n8k8.row.col.f32.tf32.tf32.f32 "
        "{%0,%1,%2,%3}, {%4,%5,%6,%7}, {%8,%9}, {%0,%1,%2,%3};"
        : "+f"(c[0]), "+f"(c[1]), "+f"(c[2]), "+f"(c[3])
        : "r"(a[0]), "r"(a[1]), "r"(a[2]), "r"(a[3]), "r"(b0), "r"(b1));
}

// ---------------- tf32 pre-round (plain + strided) -------------------------
__global__ void round_tf32_kernel(const float* __restrict__ in,
                                  float* __restrict__ o, int n4) {
    for (int i = blockIdx.x * 256 + threadIdx.x; i < n4; i += gridDim.x * 256) {
        float4 v = ((const float4*)in)[i];
        v.x = tf32r(v.x); v.y = tf32r(v.y); v.z = tf32r(v.z); v.w = tf32r(v.w);
        ((float4*)o)[i] = v;
    }
}

// copy rows of width n4row float4s from in (row stride in_ld4) to out
// (row stride out_ld4, col offset oc4), rounding to tf32.
__global__ void round_tf32_str(const float* __restrict__ in,
                               float* __restrict__ o,
                               int n4row, int in_ld4, int out_ld4, int oc4,
                               int total4) {
    for (int i = blockIdx.x * 256 + threadIdx.x; i < total4; i += gridDim.x * 256) {
        const int row = i / n4row, c = i - row * n4row;
        float4 v = ((const float4*)in)[(size_t)row * in_ld4 + c];
        v.x = tf32r(v.x); v.y = tf32r(v.y); v.z = tf32r(v.z); v.w = tf32r(v.w);
        ((float4*)o)[(size_t)row * out_ld4 + oc4 + c] = v;
    }
}

// ---------------- RoPE frequency -------------------------------------------
#define L2T_32 0.41524101186091903f   // log2(10000)/32
__device__ __forceinline__ float rope_freq(int i) {
    return exp2f(-(float)(i & 31) * L2T_32);
}

// ======================= tf32 mma.sync GEMM ================================
// C[M,N] = A[M,K] @ B[K,N]; A,B PRE-ROUNDED tf32 in gmem (no inner-loop cvt).
// M mult of 128, K mult of 32. CTA 128x128, BK=32, 256 thr (8 warps 4x2).
// mode: 0 plain; 1 q-RoPE (cols with (col%192)>=128 rotated, per-head);
//       2 pe-split (cols>=pe0 rotated -> kpe, not stored to C).
#define GSTAGE 32768
#define GSMEM (2 * GSTAGE)

__device__ __forceinline__ void g_load_stage(uint32_t sbase, int s,
        const float* __restrict__ A, int lda,
        const float* __restrict__ B, int ldb,
        int brow, int bcol, int N, int k0, int tid) {
    const uint32_t sA = sbase + s * GSTAGE;
    const uint32_t sB = sA + 16384;
#pragma unroll
    for (int it = 0; it < 4; it++) {
        const int f4 = it * 256 + tid;
        const int r = f4 >> 3, c16 = f4 & 7;
        const uint32_t dst = sA + r * 128 + ((c16 ^ (r & 7)) << 4);
        const float* src = A + (size_t)(brow + r) * lda + k0 + c16 * 4;
        asm volatile("cp.async.ca.shared.global [%0], [%1], 16;"
                     :: "r"(dst), "l"(src) : "memory");
    }
#pragma unroll
    for (int it = 0; it < 4; it++) {
        const int f4 = it * 256 + tid;
        const int k = f4 >> 5, c16 = f4 & 31;
        const uint32_t dst = sB + k * 512 + ((c16 ^ ((k & 3) << 1)) << 4);
        const float* src = B + (size_t)(k0 + k) * ldb + bcol + c16 * 4;
        const int sz = (bcol + c16 * 4 + 4 <= N) ? 16 : 0;
        asm volatile("cp.async.ca.shared.global [%0], [%1], 16, %2;"
                     :: "r"(dst), "l"(src), "r"(sz) : "memory");
    }
    asm volatile("cp.async.commit_group;" ::: "memory");
}

__global__ __launch_bounds__(256, 2) void sgemm_mma(
        const float* __restrict__ A, int lda,
        const float* __restrict__ B, int ldb,
        float* __restrict__ C, int ldc, int N, int K,
        float oscale, int rnd, int mode, int pe0,
        const int* __restrict__ pos, float* __restrict__ kpe) {
    extern __shared__ char sm[];
    const uint32_t sbase = smem_u32(sm);
    const int tid = threadIdx.x;
    const int lane = tid & 31;
    const int wid = tid >> 5;
    const int wm = wid >> 1, wn = wid & 1;
    const int brow = blockIdx.y * 128;
    const int bcol = blockIdx.x * 128;

    float acc[2][8][4];
#pragma unroll
    for (int mi = 0; mi < 2; mi++)
#pragma unroll
        for (int ni = 0; ni < 8; ni++)
#pragma unroll
            for (int j = 0; j < 4; j++) acc[mi][ni][j] = 0.f;

    const int nch = K / 32;
    g_load_stage(sbase, 0, A, lda, B, ldb, brow, bcol, N, 0, tid);

    for (int i = 0; i < nch; i++) {
        const int s = i & 1;
        if (i + 1 < nch) {
            g_load_stage(sbase, s ^ 1, A, lda, B, ldb, brow, bcol, N,
                         (i + 1) * 32, tid);
            asm volatile("cp.async.wait_group 1;" ::: "memory");
        } else {
            asm volatile("cp.async.wait_group 0;" ::: "memory");
        }
        __syncthreads();

        const float* sA = (const float*)(sm + s * GSTAGE);
        const float* sB = (const float*)(sm + s * GSTAGE + 16384);

#pragma unroll
        for (int ks = 0; ks < 4; ks++) {
            uint32_t a[2][4];
            const int q = lane >> 2, rlo = lane & 3;
            const int c0 = ks * 8 + rlo;
#pragma unroll
            for (int mi = 0; mi < 2; mi++) {
                const int r0 = wm * 32 + mi * 16 + q;
                const int r1 = r0 + 8;
                a[mi][0] = __float_as_uint(sA[r0 * 32 + ((((c0 >> 2) ^ (r0 & 7))) << 2) + rlo]);
                a[mi][1] = __float_as_uint(sA[r1 * 32 + ((((c0 >> 2) ^ (r1 & 7))) << 2) + rlo]);
                a[mi][2] = __float_as_uint(sA[r0 * 32 + (((((c0 + 4) >> 2) ^ (r0 & 7))) << 2) + rlo]);
                a[mi][3] = __float_as_uint(sA[r1 * 32 + (((((c0 + 4) >> 2) ^ (r1 & 7))) << 2) + rlo]);
            }
            uint32_t b[8][2];
            const int kb0 = ks * 8 + rlo, kb1 = kb0 + 4;
#pragma unroll
            for (int ni = 0; ni < 8; ni++) {
                const int n = wn * 64 + ni * 8 + q;
                b[ni][0] = __float_as_uint(sB[kb0 * 128 + (((n >> 2) ^ ((kb0 & 3) << 1)) << 2) + (n & 3)]);
                b[ni][1] = __float_as_uint(sB[kb1 * 128 + (((n >> 2) ^ ((kb1 & 3) << 1)) << 2) + (n & 3)]);
            }
#pragma unroll
            for (int mi = 0; mi < 2; mi++)
#pragma unroll
                for (int ni = 0; ni < 8; ni++)
                    mma_tf32(acc[mi][ni], a[mi], b[ni][0], b[ni][1]);
        }
        __syncthreads();
    }

    // ---- epilogue: oscale, optional RoPE, optional tf32 round, store ----
    const int q = lane >> 2, rlo = lane & 3;
#pragma unroll
    for (int mi = 0; mi < 2; mi++) {
        const int r0 = brow + wm * 32 + mi * 16 + q;
        const int r1 = r0 + 8;
        float fp0 = 0.f, fp1 = 0.f;
        if (mode != 0) { fp0 = (float)pos[r0]; fp1 = (float)pos[r1]; }
#pragma unroll
        for (int ni = 0; ni < 8; ni++) {
            const int col = bcol + wn * 64 + ni * 8 + rlo * 2;
            if (col >= N) continue;
            float x0 = acc[mi][ni][0] * oscale, x1 = acc[mi][ni][1] * oscale;
            float x2 = acc[mi][ni][2] * oscale, x3 = acc[mi][ni][3] * oscale;

            if (mode == 1) {
                const int d = col % QDIM;
                if (d >= DQ) {
                    const int i0 = d - DQ;             // even
                    const float f0 = rope_freq(i0), f1 = rope_freq(i0 + 1);
                    float s0, c0, s1, c1;
                    sincosf(fp0 * f0, &s0, &c0);
                    sincosf(fp0 * f1, &s1, &c1);
                    float nx0 = x0 * c0 - x1 * s0;
                    float nx1 = x1 * c1 + x0 * s1;
                    x0 = nx0; x1 = nx1;
                    sincosf(fp1 * f0, &s0, &c0);
                    sincosf(fp1 * f1, &s1, &c1);
                    float nx2 = x2 * c0 - x3 * s0;
                    float nx3 = x3 * c1 + x2 * s1;
                    x2 = nx2; x3 = nx3;
                }
            } else if (mode == 2 && col >= pe0) {
                const int i0 = col - pe0;              // even, [0,64)
                const float f0 = rope_freq(i0), f1 = rope_freq(i0 + 1);
                float s0, c0, s1, c1;
                sincosf(fp0 * f0, &s0, &c0);
                sincosf(fp0 * f1, &s1, &c1);
                *(float2*)&kpe[(size_t)r0 * DR + i0] =
                    make_float2(tf32r(x0 * c0 - x1 * s0), tf32r(x1 * c1 + x0 * s1));
                sincosf(fp1 * f0, &s0, &c0);
                sincosf(fp1 * f1, &s1, &c1);
                *(float2*)&kpe[(size_t)r1 * DR + i0] =
                    make_float2(tf32r(x2 * c0 - x3 * s0), tf32r(x3 * c1 + x2 * s1));
                continue;  // pe cols not written to C
            }

            if (rnd) {
                x0 = tf32r(x0); x1 = tf32r(x1); x2 = tf32r(x2); x3 = tf32r(x3);
            }
            *(float2*)&C[(size_t)r0 * ldc + col] = make_float2(x0, x1);
            *(float2*)&C[(size_t)r1 * ldc + col] = make_float2(x2, x3);
        }
    }
}

// ---------------- RMSNorm in place (writes tf32-rounded) --------------------
__global__ void rmsnorm_kernel(float* __restrict__ x, const float* __restrict__ g,
                               int width, int stride) {
    const int row = blockIdx.x;
    float* p = x + (size_t)row * stride;
    const int tid = threadIdx.x;
    float s = 0.f;
    for (int i = tid; i < width; i += 256) {
        float v = p[i];
        s += v * v;
    }
    __shared__ float red[256];
    red[tid] = s;
    __syncthreads();
    for (int o = 128; o > 0; o >>= 1) {
        if (tid < o) red[tid] += red[tid + o];
        __syncthreads();
    }
    const float inv = rsqrtf(red[0] / (float)width + 1e-6f);
    for (int i = tid; i < width; i += 256) p[i] = tf32r(p[i] * inv * g[i]);
}

// ================ flash attention, tf32 mma, log2-domain softmax ===========
#define FQP 196
#define FKP 196
#define FVP 136
#define FPP 72
#define FLASH_SMEM ((128 * FQP + 64 * FKP + 64 * FVP + 128 * FPP) * 4)  // 222208

__global__ __launch_bounds__(256, 1) void flash_tc(
        const float* __restrict__ q, const float* __restrict__ kvup,
        const float* __restrict__ kpe, float* __restrict__ out) {
    const int ib = blockIdx.x;
    const int h = blockIdx.y;
    const int tid = threadIdx.x;
    const int lane = tid & 31;
    const int wid = tid >> 5;

    extern __shared__ float fs[];
    float* sQ = fs;
    float* sK = sQ + 128 * FQP;
    float* sV = sK + 64 * FKP;
    float* sP = sV + 64 * FVP;

    for (int idx = tid; idx < 128 * 48; idx += 256) {
        const int r = idx / 48, d4 = idx % 48;
        *(float4*)&sQ[r * FQP + d4 * 4] =
            *(const float4*)&q[(size_t)(ib * 128 + r) * QW + h * QDIM + d4 * 4];
    }

    const int r = lane >> 2, c2 = lane & 3;
    const int qr0 = ib * 128 + wid * 16 + r;
    float m0 = -INFINITY, m1 = -INFINITY, l0 = 0.f, l1 = 0.f;
    float O[16][4];
#pragma unroll
    for (int nt = 0; nt < 16; nt++)
#pragma unroll
        for (int j = 0; j < 4; j++) O[nt][j] = 0.f;

    const int njb = 2 * ib + 2;
    for (int jb = 0; jb < njb; jb++) {
        __syncthreads();
        for (int idx = tid; idx < 64 * 48; idx += 256) {
            const int rr = idx / 48, d4 = idx % 48;
            const int kt = jb * 64 + rr;
            float4 v;
            if (d4 < 32) v = *(const float4*)&kvup[(size_t)kt * KVUPW + h * 256 + d4 * 4];
            else         v = *(const float4*)&kpe[(size_t)kt * DR + (d4 - 32) * 4];
            *(float4*)&sK[rr * FKP + d4 * 4] = v;
        }
        for (int idx = tid; idx < 64 * 32; idx += 256) {
            const int rr = idx >> 5, d4 = idx & 31;
            *(float4*)&sV[rr * FVP + d4 * 4] =
                *(const float4*)&kvup[(size_t)(jb * 64 + rr) * KVUPW + h * 256 + 128 + d4 * 4];
        }
        __syncthreads();

        float S[8][4];
#pragma unroll
        for (int nt = 0; nt < 8; nt++)
#pragma unroll
            for (int j = 0; j < 4; j++) S[nt][j] = 0.f;

#pragma unroll
        for (int ks = 0; ks < 24; ks++) {
            uint32_t a[4];
            const int base = (wid * 16 + r) * FQP + ks * 8 + c2;
            a[0] = __float_as_uint(sQ[base]);
            a[1] = __float_as_uint(sQ[base + 8 * FQP]);
            a[2] = __float_as_uint(sQ[base + 4]);
            a[3] = __float_as_uint(sQ[base + 8 * FQP + 4]);
#pragma unroll
            for (int nt = 0; nt < 8; nt++) {
                const int kb = (nt * 8 + r) * FKP + ks * 8 + c2;
                mma_tf32(S[nt], a, __float_as_uint(sK[kb]),
                         __float_as_uint(sK[kb + 4]));
            }
        }

        if (jb >= 2 * ib) {
#pragma unroll
            for (int nt = 0; nt < 8; nt++) {
                const int kc = jb * 64 + nt * 8 + c2 * 2;
                if (kc > qr0)     S[nt][0] = -1e30f;
                if (kc + 1 > qr0) S[nt][1] = -1e30f;
                if (kc > qr0 + 8)     S[nt][2] = -1e30f;
                if (kc + 1 > qr0 + 8) S[nt][3] = -1e30f;
            }
        }

        float mx0 = -INFINITY, mx1 = -INFINITY;
#pragma unroll
        for (int nt = 0; nt < 8; nt++) {
            mx0 = fmaxf(mx0, fmaxf(S[nt][0], S[nt][1]));
            mx1 = fmaxf(mx1, fmaxf(S[nt][2], S[nt][3]));
        }
        mx0 = fmaxf(mx0, __shfl_xor_sync(0xffffffffu, mx0, 1));
        mx0 = fmaxf(mx0, __shfl_xor_sync(0xffffffffu, mx0, 2));
        mx1 = fmaxf(mx1, __shfl_xor_sync(0xffffffffu, mx1, 1));
        mx1 = fmaxf(mx1, __shfl_xor_sync(0xffffffffu, mx1, 2));
        const float mn0 = fmaxf(m0, mx0), mn1 = fmaxf(m1, mx1);
        const float al0 = ex2f(m0 - mn0), al1 = ex2f(m1 - mn1);
        m0 = mn0; m1 = mn1;
        float rs0 = 0.f, rs1 = 0.f;
#pragma unroll
        for (int nt = 0; nt < 8; nt++) {
            const float p0 = ex2f(S[nt][0] - mn0);
            const float p1 = ex2f(S[nt][1] - mn0);
            const float p2 = ex2f(S[nt][2] - mn1);
            const float p3 = ex2f(S[nt][3] - mn1);
            rs0 += p0 + p1;
            rs1 += p2 + p3;
            const int pr = (wid * 16 + r) * FPP + nt * 8 + c2 * 2;
            *(float2*)&sP[pr] = make_float2(tf32r(p0), tf32r(p1));
            *(float2*)&sP[pr + 8 * FPP] = make_float2(tf32r(p2), tf32r(p3));
        }
        rs0 += __shfl_xor_sync(0xffffffffu, rs0, 1);
        rs0 += __shfl_xor_sync(0xffffffffu, rs0, 2);
        rs1 += __shfl_xor_sync(0xffffffffu, rs1, 1);
        rs1 += __shfl_xor_sync(0xffffffffu, rs1, 2);
        l0 = l0 * al0 + rs0;
        l1 = l1 * al1 + rs1;
#pragma unroll
        for (int nt = 0; nt < 16; nt++) {
            O[nt][0] *= al0; O[nt][1] *= al0;
            O[nt][2] *= al1; O[nt][3] *= al1;
        }
        __syncwarp();

#pragma unroll
        for (int kf = 0; kf < 8; kf++) {
            uint32_t a[4];
            const int pb = (wid * 16 + r) * FPP + kf * 8 + c2;
            a[0] = __float_as_uint(sP[pb]);
            a[1] = __float_as_uint(sP[pb + 8 * FPP]);
            a[2] = __float_as_uint(sP[pb + 4]);
            a[3] = __float_as_uint(sP[pb + 8 * FPP + 4]);
#pragma unroll
            for (int nt = 0; nt < 16; nt++) {
                const int vb = (kf * 8 + c2) * FVP + nt * 8 + r;
                mma_tf32(O[nt], a, __float_as_uint(sV[vb]),
                         __float_as_uint(sV[vb + 4 * FVP]));
            }
        }
    }

    const float inv0 = 1.f / l0, inv1 = 1.f / l1;
    const int row0 = ib * 128 + wid * 16 + r;
#pragma unroll
    for (int nt = 0; nt < 16; nt++) {
        const int col = h * DV + nt * 8 + c2 * 2;
        *(float2*)&out[(size_t)row0 * ATTNW + col] =
            make_float2(tf32r(O[nt][0] * inv0), tf32r(O[nt][1] * inv0));
        *(float2*)&out[(size_t)(row0 + 8) * ATTNW + col] =
            make_float2(tf32r(O[nt][2] * inv1), tf32r(O[nt][3] * inv1));
    }
}

// ---------------- launch -----------------------------------------------------
extern "C" void kernel_launch(void* const* d_in, const int* in_sizes, int n_in,
                              void* d_out, int out_size) {
    const int* positions = (const int*)d_in[0];
    const float* hidden = (const float*)d_in[1];
    const float* w_qa = (const float*)d_in[2];
    const float* gamma_q = (const float*)d_in[3];
    const float* w_qb = (const float*)d_in[4];
    const float* w_kva = (const float*)d_in[5];
    const float* gamma_kv = (const float*)d_in[6];
    const float* w_kvb = (const float*)d_in[7];
    const float* w_o = (const float*)d_in[8];
    float* out = (float*)d_out;

    float *cmb, *q, *kvup, *kpe, *attn;
    float *hid_t, *wcmb_t, *wqb_t, *wkvb_t, *wo_t;
    cudaGetSymbolAddress((void**)&cmb, g_cmb);
    cudaGetSymbolAddress((void**)&q, g_q);
    cudaGetSymbolAddress((void**)&kvup, g_kvup);
    cudaGetSymbolAddress((void**)&kpe, g_kpe);
    cudaGetSymbolAddress((void**)&attn, g_attn);
    cudaGetSymbolAddress((void**)&hid_t, g_hid_t);
    cudaGetSymbolAddress((void**)&wcmb_t, g_wcmb_t);
    cudaGetSymbolAddress((void**)&wqb_t, g_wqb_t);
    cudaGetSymbolAddress((void**)&wkvb_t, g_wkvb_t);
    cudaGetSymbolAddress((void**)&wo_t, g_wo_t);

    cudaFuncSetAttribute(sgemm_mma, cudaFuncAttributeMaxDynamicSharedMemorySize, GSMEM);
    cudaFuncSetAttribute(flash_tc, cudaFuncAttributeMaxDynamicSharedMemorySize,
                         FLASH_SMEM);

    const float SCALE_L2E = 0.07216878364870323f * 1.4426950408889634f;
    const int MB = T_TOK / 128;  // 16

    // 1-5: tf32 pre-rounds (hidden; w_qa|w_kva combined; w_qb; w_kvb)
    round_tf32_kernel<<<2048, 256>>>(hidden, hid_t, T_TOK * HIDDEN / 4);
    round_tf32_str<<<2048, 256>>>(w_qa, wcmb_t, QLORA / 4, QLORA / 4, CMBW / 4,
                                  0, HIDDEN * QLORA / 4);
    round_tf32_str<<<2048, 256>>>(w_kva, wcmb_t, KV_W / 4, KV_W / 4, CMBW / 4,
                                  QLORA / 4, HIDDEN * KV_W / 4);
    round_tf32_kernel<<<2048, 256>>>(w_qb, wqb_t, QLORA * QW / 4);
    round_tf32_kernel<<<2048, 256>>>(w_kvb, wkvb_t, KVLORA * KVUPW / 4);
    // 6: merged down-proj: [q_a | kv_c | k_pe] = hid @ [w_qa|w_kva]  [2048,2112]
    //    cols >= 2048 roped -> kpe (profiled launch)
    sgemm_mma<<<dim3((CMBW + 127) / 128, MB), 256, GSMEM>>>(
        hid_t, HIDDEN, wcmb_t, CMBW, cmb, CMBW, CMBW, HIDDEN, 1.f, 0, 2,
        QLORA + KVLORA, positions, kpe);
    // 7,8: rmsnorm in place on the combined buffer
    rmsnorm_kernel<<<T_TOK, 256>>>(cmb, gamma_q, QLORA, CMBW);
    rmsnorm_kernel<<<T_TOK, 256>>>(cmb + QLORA, gamma_kv, KVLORA, CMBW);
    // 9: q = (q_c @ w_qb) * scale*log2e, q-RoPE fused, tf32   [2048,6144]
    sgemm_mma<<<dim3(QW / 128, MB), 256, GSMEM>>>(
        cmb, CMBW, wqb_t, QW, q, QW, QW, QLORA, SCALE_L2E, 1, 1, 0,
        positions, kpe);
    // 10: kv_up = kv_c @ w_kvb, tf32 [2048,8192]
    sgemm_mma<<<dim3(KVUPW / 128, MB), 256, GSMEM>>>(
        cmb + QLORA, CMBW, wkvb_t, KVUPW, kvup, KVUPW, KVUPW, KVLORA,
        1.f, 1, 0, 0, positions, kpe);
    // 11: pre-round w_o (needed only for the final GEMM)
    round_tf32_kernel<<<2048, 256>>>(w_o, wo_t, ATTNW * HIDDEN / 4);
    // 12: attention (tensor-core, log2-domain softmax)
    flash_tc<<<dim3(T_TOK / 128, NH), 256, FLASH_SMEM>>>(q, kvup, kpe, attn);
    // 13: out = attn @ w_o           [2048,5120]
    sgemm_mma<<<dim3(HIDDEN / 128, MB), 256, GSMEM>>>(
        attn, ATTNW, wo_t, HIDDEN, out, HIDDEN, HIDDEN, ATTNW, 1.f, 0, 0, 0,
        positions, kpe);
}

// round 11
// speedup vs baseline: 1.6523x; 1.4302x over previous
#include <cuda_runtime.h>
#include <cuda_fp16.h>
#include <math.h>
#include <stdint.h>

#define T_TOK 2048
#define HIDDEN 5120
#define NH 32
#define DQ 128
#define DR 64
#define DV 128
#define QLORA 1536
#define KVLORA 512
#define KV_W (KVLORA + DR)        // 576
#define QDIM (DQ + DR)            // 192
#define KVUPW (NH * (DQ + DV))    // 8192
#define QW (NH * QDIM)            // 6144
#define ATTNW (NH * DV)           // 4096
#define CMBW (QLORA + KV_W)       // 2112

// ---------------- scratch (device globals; no runtime allocation) ----------
__device__ __half g_hid_h[T_TOK * HIDDEN];
__device__ __half g_wcmbT[CMBW * HIDDEN];    // [2112][5120] K-major
__device__ __half g_wqbT[QW * QLORA];        // [6144][1536]
__device__ __half g_wkvbT[KVUPW * KVLORA];   // [8192][512]
__device__ __half g_woT[HIDDEN * ATTNW];     // [5120][4096]
__device__ __half g_cmbh[T_TOK * CMBW];
__device__ __half g_qh[T_TOK * QW];
__device__ __half g_kvuph[T_TOK * KVUPW];
__device__ __half g_kpeh[T_TOK * DR];
__device__ __half g_attnh[T_TOK * ATTNW];

// ======================= helpers ===========================================
__device__ __forceinline__ uint32_t smem_u32(const void* p) {
    uint32_t a;
    asm("{ .reg .u64 t; cvta.to.shared.u64 t, %1; cvt.u32.u64 %0, t; }"
        : "=r"(a) : "l"(p));
    return a;
}

__device__ __forceinline__ float ex2f(float x) {
    float y;
    asm("ex2.approx.ftz.f32 %0, %1;" : "=f"(y) : "f"(x));
    return y;
}

__device__ __forceinline__ void mma_f16(float c[4], const uint32_t a[4],
                                        uint32_t b0, uint32_t b1) {
    asm volatile(
        "mma.sync.aligned.m16n8k16.row.col.f32.f16.f16.f32 "
        "{%0,%1,%2,%3}, {%4,%5,%6,%7}, {%8,%9}, {%0,%1,%2,%3};"
        : "+f"(c[0]), "+f"(c[1]), "+f"(c[2]), "+f"(c[3])
        : "r"(a[0]), "r"(a[1]), "r"(a[2]), "r"(a[3]), "r"(b0), "r"(b1));
}

__device__ __forceinline__ uint32_t h2u(__half2 h) {
    return *reinterpret_cast<uint32_t*>(&h);
}

// ---------------- fp32 -> fp16 conversion kernels --------------------------
__global__ void cvt_h_kernel(const float* __restrict__ in,
                             __half* __restrict__ o, int n4) {
    __half2* o2 = (__half2*)o;
    for (int i = blockIdx.x * 256 + threadIdx.x; i < n4; i += gridDim.x * 256) {
        float4 v = ((const float4*)in)[i];
        o2[2 * i] = __floats2half2_rn(v.x, v.y);
        o2[2 * i + 1] = __floats2half2_rn(v.z, v.w);
    }
}

// transpose + convert: in [Kd][Nd] fp32 -> out rows [orow + n][Kd] fp16
__global__ void cvtT_kernel(const float* __restrict__ in,
                            __half* __restrict__ out,
                            int Kd, int Nd, int orow) {
    __shared__ float t[32][33];
    const int n0 = blockIdx.x * 32, k0 = blockIdx.y * 32;
    const int x = threadIdx.x, y = threadIdx.y;  // (32,8)
#pragma unroll
    for (int j = 0; j < 4; j++)
        t[y + 8 * j][x] = in[(size_t)(k0 + y + 8 * j) * Nd + n0 + x];
    __syncthreads();
#pragma unroll
    for (int j = 0; j < 4; j++)
        out[(size_t)(orow + n0 + y + 8 * j) * Kd + k0 + x] =
            __float2half_rn(t[x][y + 8 * j]);
}

// ---------------- RoPE frequency -------------------------------------------
#define L2T_32 0.41524101186091903f   // log2(10000)/32
__device__ __forceinline__ float rope_freq(int i) {
    return exp2f(-(float)(i & 31) * L2T_32);
}

// ======================= fp16 mma.sync GEMM ================================
// C[M,N] = A[M,K] @ B[K,N]; A fp16 row-major [M][K]; B pre-transposed fp16
// [N][K]. M mult of 128, K mult of 32. CTA 128x128, BK=32, 3-stage cp.async,
// 256 thr (8 warps 4x2, warp tile 32x64, m16n8k16).
// smem rows: 16 data u32 + 4 pad = stride 20 u32 (conflict-free frags).
#define RS 20
#define GSTG (128 * RS * 4)          // 10240 B per operand
#define GSTAGE (2 * GSTG)            // 20480 B per stage
#define GSMEM (3 * GSTAGE)           // 61440 B

__device__ __forceinline__ void g_load(uint32_t sbase, int s,
        const __half* __restrict__ A, int lda,
        const __half* __restrict__ BT, int ldb,
        int brow, int bcol, int N, int k0, int tid) {
    const uint32_t sA = sbase + s * GSTAGE;
    const uint32_t sB = sA + GSTG;
#pragma unroll
    for (int it = 0; it < 2; it++) {
        const int f = it * 256 + tid;
        const int r = f >> 2, c = f & 3;
        const uint32_t dst = sA + (r * RS + c * 4) * 4;
        const __half* src = A + (size_t)(brow + r) * lda + k0 + c * 8;
        asm volatile("cp.async.ca.shared.global [%0], [%1], 16;"
                     :: "r"(dst), "l"(src) : "memory");
    }
#pragma unroll
    for (int it = 0; it < 2; it++) {
        const int f = it * 256 + tid;
        const int r = f >> 2, c = f & 3;
        const uint32_t dst = sB + (r * RS + c * 4) * 4;
        const __half* src = BT + (size_t)(bcol + r) * ldb + k0 + c * 8;
        const int sz = (bcol + r < N) ? 16 : 0;
        asm volatile("cp.async.ca.shared.global [%0], [%1], 16, %2;"
                     :: "r"(dst), "l"(src), "r"(sz) : "memory");
    }
    asm volatile("cp.async.commit_group;" ::: "memory");
}

// mode: 0 plain; 1 q-RoPE ((col%192)>=128 rotated); 2 pe-split (col>=pe0 ->
// kpe). outfp32: C treated as float* (final output), else __half*.
__global__ __launch_bounds__(256, 2) void gemm_h(
        const __half* __restrict__ A, int lda,
        const __half* __restrict__ BT, int ldb,
        void* __restrict__ Cv, int ldc, int N, int K,
        float oscale, int mode, int pe0, int outfp32,
        const int* __restrict__ pos, __half* __restrict__ kpe) {
    extern __shared__ char sm[];
    const uint32_t sbase = smem_u32(sm);
    const int tid = threadIdx.x;
    const int lane = tid & 31;
    const int wid = tid >> 5;
    const int wm = wid >> 1, wn = wid & 1;
    const int brow = blockIdx.y * 128;
    const int bcol = blockIdx.x * 128;
    const int r = lane >> 2, c2 = lane & 3;

    float acc[2][8][4];
#pragma unroll
    for (int mi = 0; mi < 2; mi++)
#pragma unroll
        for (int ni = 0; ni < 8; ni++)
#pragma unroll
            for (int j = 0; j < 4; j++) acc[mi][ni][j] = 0.f;

    const int nch = K / 32;
    g_load(sbase, 0, A, lda, BT, ldb, brow, bcol, N, 0, tid);
    g_load(sbase, 1, A, lda, BT, ldb, brow, bcol, N, 32, tid);

    for (int i = 0; i < nch; i++) {
        const int s = i % 3;
        if (i + 1 < nch) {
            asm volatile("cp.async.wait_group 1;" ::: "memory");
        } else {
            asm volatile("cp.async.wait_group 0;" ::: "memory");
        }
        __syncthreads();

        const uint32_t* sA = (const uint32_t*)(sm + s * GSTAGE);
        const uint32_t* sB = sA + 128 * RS;

#pragma unroll
        for (int t = 0; t < 2; t++) {
            uint32_t a[2][4];
#pragma unroll
            for (int mi = 0; mi < 2; mi++) {
                const int row0 = wm * 32 + mi * 16 + r;
                a[mi][0] = sA[row0 * RS + t * 8 + c2];
                a[mi][1] = sA[(row0 + 8) * RS + t * 8 + c2];
                a[mi][2] = sA[row0 * RS + t * 8 + c2 + 4];
                a[mi][3] = sA[(row0 + 8) * RS + t * 8 + c2 + 4];
            }
#pragma unroll
            for (int ni = 0; ni < 8; ni++) {
                const int n = wn * 64 + ni * 8 + r;
                const uint32_t b0 = sB[n * RS + t * 8 + c2];
                const uint32_t b1 = sB[n * RS + t * 8 + c2 + 4];
                mma_f16(acc[0][ni], a[0], b0, b1);
                mma_f16(acc[1][ni], a[1], b0, b1);
            }
        }
        if (i + 2 < nch)
            g_load(sbase, (i + 2) % 3, A, lda, BT, ldb, brow, bcol, N,
                   (i + 2) * 32, tid);
    }

    // ---- epilogue ----
    __half* Ch = (__half*)Cv;
    float* Cf = (float*)Cv;
    const int rlo = c2;
#pragma unroll
    for (int mi = 0; mi < 2; mi++) {
        const int r0 = brow + wm * 32 + mi * 16 + r;
        const int r1 = r0 + 8;
        float fp0 = 0.f, fp1 = 0.f;
        if (mode != 0) { fp0 = (float)pos[r0]; fp1 = (float)pos[r1]; }
#pragma unroll
        for (int ni = 0; ni < 8; ni++) {
            const int col = bcol + wn * 64 + ni * 8 + rlo * 2;
            if (col >= N) continue;
            float x0 = acc[mi][ni][0] * oscale, x1 = acc[mi][ni][1] * oscale;
            float x2 = acc[mi][ni][2] * oscale, x3 = acc[mi][ni][3] * oscale;

            if (mode == 1) {
                const int d = col % QDIM;
                if (d >= DQ) {
                    const int i0 = d - DQ;
                    const float f0 = rope_freq(i0), f1 = rope_freq(i0 + 1);
                    float s0, c0, s1, c1;
                    sincosf(fp0 * f0, &s0, &c0);
                    sincosf(fp0 * f1, &s1, &c1);
                    float nx0 = x0 * c0 - x1 * s0;
                    float nx1 = x1 * c1 + x0 * s1;
                    x0 = nx0; x1 = nx1;
                    sincosf(fp1 * f0, &s0, &c0);
                    sincosf(fp1 * f1, &s1, &c1);
                    float nx2 = x2 * c0 - x3 * s0;
                    float nx3 = x3 * c1 + x2 * s1;
                    x2 = nx2; x3 = nx3;
                }
            } else if (mode == 2 && col >= pe0) {
                const int i0 = col - pe0;
                const float f0 = rope_freq(i0), f1 = rope_freq(i0 + 1);
                float s0, c0, s1, c1;
                sincosf(fp0 * f0, &s0, &c0);
                sincosf(fp0 * f1, &s1, &c1);
                ((__half2*)kpe)[((size_t)r0 * DR + i0) >> 1] =
                    __floats2half2_rn(x0 * c0 - x1 * s0, x1 * c1 + x0 * s1);
                sincosf(fp1 * f0, &s0, &c0);
                sincosf(fp1 * f1, &s1, &c1);
                ((__half2*)kpe)[((size_t)r1 * DR + i0) >> 1] =
                    __floats2half2_rn(x2 * c0 - x3 * s0, x3 * c1 + x2 * s1);
                continue;
            }

            if (outfp32) {
                *(float2*)&Cf[(size_t)r0 * ldc + col] = make_float2(x0, x1);
                *(float2*)&Cf[(size_t)r1 * ldc + col] = make_float2(x2, x3);
            } else {
                ((__half2*)Ch)[((size_t)r0 * ldc + col) >> 1] =
                    __floats2half2_rn(x0, x1);
                ((__half2*)Ch)[((size_t)r1 * ldc + col) >> 1] =
                    __floats2half2_rn(x2, x3);
            }
        }
    }
}

// ---------------- RMSNorm in place on fp16 ----------------------------------
__global__ void rmsnorm_h(__half* __restrict__ x, const float* __restrict__ g,
                          int width, int stride) {
    const int row = blockIdx.x;
    __half2* p = (__half2*)(x + (size_t)row * stride);
    const int tid = threadIdx.x;
    const int w2 = width >> 1;
    float s = 0.f;
    for (int i = tid; i < w2; i += 256) {
        float2 f = __half22float2(p[i]);
        s += f.x * f.x + f.y * f.y;
    }
    __shared__ float red[256];
    red[tid] = s;
    __syncthreads();
    for (int o = 128; o > 0; o >>= 1) {
        if (tid < o) red[tid] += red[tid + o];
        __syncthreads();
    }
    const float inv = rsqrtf(red[0] / (float)width + 1e-6f);
    for (int i = tid; i < w2; i += 256) {
        float2 f = __half22float2(p[i]);
        p[i] = __floats2half2_rn(f.x * inv * g[2 * i], f.y * inv * g[2 * i + 1]);
    }
}

// ================ flash attention, fp16 mma, log2-domain softmax ===========
// grid (16, 32): 128 q rows/CTA, 8 warps (16 rows each), k-tiles of 64.
// Q pre-scaled by (DQ+DR)^-0.5 * log2(e). All operands fp16, accum fp32.
// u32 strides (≡4 mod 8 -> conflict-free fragment loads):
#define QS 100   // sQ [128 q][96 u32 data]
#define KS 100   // sK [64 tok][96 u32]
#define VS 36    // sV [128 dv][32 u32]  (V transposed)
#define PS 36    // sP [128 q][32 u32]
#define FLASH_SMEM ((128 * QS + 64 * KS + 128 * VS + 128 * PS) * 4)  // 113664

__global__ __launch_bounds__(256, 1) void flash_h(
        const __half* __restrict__ q, const __half* __restrict__ kvup,
        const __half* __restrict__ kpe, __half* __restrict__ out) {
    const int ib = blockIdx.x;
    const int h = blockIdx.y;
    const int tid = threadIdx.x;
    const int lane = tid & 31;
    const int wid = tid >> 5;
    const int r = lane >> 2, c2 = lane & 3;

    extern __shared__ uint32_t fs[];
    uint32_t* sQ = fs;                 // 12800 u32
    uint32_t* sK = sQ + 128 * QS;      // 6400
    uint32_t* sV = sK + 64 * KS;       // 4608
    uint32_t* sP = sV + 128 * VS;      // 4608

    // Q tile: 128 rows x 192 halves (96 u32), float4 copies
    for (int idx = tid; idx < 128 * 24; idx += 256) {
        const int rr = idx / 24, d4 = idx % 24;
        *(float4*)&sQ[rr * QS + d4 * 4] =
            *(const float4*)(q + (size_t)(ib * 128 + rr) * QW + h * QDIM + d4 * 8);
    }

    const int qr0 = ib * 128 + wid * 16 + r;
    float m0 = -INFINITY, m1 = -INFINITY, l0 = 0.f, l1 = 0.f;
    float O[16][4];
#pragma unroll
    for (int nt = 0; nt < 16; nt++)
#pragma unroll
        for (int j = 0; j < 4; j++) O[nt][j] = 0.f;

    const uint32_t* kvu = (const uint32_t*)kvup;
    const int njb = 2 * ib + 2;
    for (int jb = 0; jb < njb; jb++) {
        __syncthreads();
        // K tile: 64 tok x 192 halves (nope | roped pe)
        for (int idx = tid; idx < 64 * 24; idx += 256) {
            const int rr = idx / 24, d4 = idx % 24;
            const int kt = jb * 64 + rr;
            float4 v;
            if (d4 < 16)
                v = *(const float4*)(kvup + (size_t)kt * KVUPW + h * 256 + d4 * 8);
            else
                v = *(const float4*)(kpe + (size_t)kt * DR + (d4 - 16) * 8);
            *(float4*)&sK[rr * KS + d4 * 4] = v;
        }
        // V tile transposed: [dv 128][tok 64] via byte_perm repack
        for (int idx = tid; idx < 2048; idx += 256) {
            const int dvp = idx & 63, tkp = idx >> 6;
            const size_t base =
                ((size_t)(jb * 64 + 2 * tkp) * KVUPW + h * 256 + 128) >> 1;
            const uint32_t a = kvu[base + dvp];
            const uint32_t b = kvu[base + (KVUPW >> 1) + dvp];
            sV[(2 * dvp) * VS + tkp] = __byte_perm(a, b, 0x5410);
            sV[(2 * dvp + 1) * VS + tkp] = __byte_perm(a, b, 0x7632);
        }
        __syncthreads();

        // ---- S = Q K^T ----
        float S[8][4];
#pragma unroll
        for (int nt = 0; nt < 8; nt++)
#pragma unroll
            for (int j = 0; j < 4; j++) S[nt][j] = 0.f;

        const int row0 = wid * 16 + r;
#pragma unroll
        for (int ks = 0; ks < 12; ks++) {
            uint32_t a[4];
            a[0] = sQ[row0 * QS + ks * 8 + c2];
            a[1] = sQ[(row0 + 8) * QS + ks * 8 + c2];
            a[2] = sQ[row0 * QS + ks * 8 + c2 + 4];
            a[3] = sQ[(row0 + 8) * QS + ks * 8 + c2 + 4];
#pragma unroll
            for (int nt = 0; nt < 8; nt++) {
                const int n = nt * 8 + r;
                mma_f16(S[nt], a, sK[n * KS + ks * 8 + c2],
                        sK[n * KS + ks * 8 + c2 + 4]);
            }
        }

        // ---- causal mask ----
        if (jb >= 2 * ib) {
#pragma unroll
            for (int nt = 0; nt < 8; nt++) {
                const int kc = jb * 64 + nt * 8 + c2 * 2;
                if (kc > qr0)     S[nt][0] = -1e30f;
                if (kc + 1 > qr0) S[nt][1] = -1e30f;
                if (kc > qr0 + 8)     S[nt][2] = -1e30f;
                if (kc + 1 > qr0 + 8) S[nt][3] = -1e30f;
            }
        }

        // ---- online softmax (log2 domain) ----
        float mx0 = -INFINITY, mx1 = -INFINITY;
#pragma unroll
        for (int nt = 0; nt < 8; nt++) {
            mx0 = fmaxf(mx0, fmaxf(S[nt][0], S[nt][1]));
            mx1 = fmaxf(mx1, fmaxf(S[nt][2], S[nt][3]));
        }
        mx0 = fmaxf(mx0, __shfl_xor_sync(0xffffffffu, mx0, 1));
        mx0 = fmaxf(mx0, __shfl_xor_sync(0xffffffffu, mx0, 2));
        mx1 = fmaxf(mx1, __shfl_xor_sync(0xffffffffu, mx1, 1));
        mx1 = fmaxf(mx1, __shfl_xor_sync(0xffffffffu, mx1, 2));
        const float mn0 = fmaxf(m0, mx0), mn1 = fmaxf(m1, mx1);
        const float al0 = ex2f(m0 - mn0), al1 = ex2f(m1 - mn1);
        m0 = mn0; m1 = mn1;
        float rs0 = 0.f, rs1 = 0.f;
#pragma unroll
        for (int nt = 0; nt < 8; nt++) {
            const float p0 = ex2f(S[nt][0] - mn0);
            const float p1 = ex2f(S[nt][1] - mn0);
            const float p2 = ex2f(S[nt][2] - mn1);
            const float p3 = ex2f(S[nt][3] - mn1);
            rs0 += p0 + p1;
            rs1 += p2 + p3;
            sP[row0 * PS + nt * 4 + c2] = h2u(__floats2half2_rn(p0, p1));
            sP[(row0 + 8) * PS + nt * 4 + c2] = h2u(__floats2half2_rn(p2, p3));
        }
        rs0 += __shfl_xor_sync(0xffffffffu, rs0, 1);
        rs0 += __shfl_xor_sync(0xffffffffu, rs0, 2);
        rs1 += __shfl_xor_sync(0xffffffffu, rs1, 1);
        rs1 += __shfl_xor_sync(0xffffffffu, rs1, 2);
        l0 = l0 * al0 + rs0;
        l1 = l1 * al1 + rs1;
#pragma unroll
        for (int nt = 0; nt < 16; nt++) {
            O[nt][0] *= al0; O[nt][1] *= al0;
            O[nt][2] *= al1; O[nt][3] *= al1;
        }
        __syncwarp();

        // ---- O += P V ----
#pragma unroll
        for (int kf = 0; kf < 4; kf++) {
            uint32_t a[4];
            a[0] = sP[row0 * PS + kf * 8 + c2];
            a[1] = sP[(row0 + 8) * PS + kf * 8 + c2];
            a[2] = sP[row0 * PS + kf * 8 + c2 + 4];
            a[3] = sP[(row0 + 8) * PS + kf * 8 + c2 + 4];
#pragma unroll
            for (int nt = 0; nt < 16; nt++) {
                const int n = nt * 8 + r;
                mma_f16(O[nt], a, sV[n * VS + kf * 8 + c2],
                        sV[n * VS + kf * 8 + c2 + 4]);
            }
        }
    }

    // ---- epilogue: normalize, store fp16 ----
    const float inv0 = 1.f / l0, inv1 = 1.f / l1;
    const int row0 = ib * 128 + wid * 16 + r;
    __half2* out2 = (__half2*)out;
#pragma unroll
    for (int nt = 0; nt < 16; nt++) {
        const int col = h * DV + nt * 8 + c2 * 2;
        out2[((size_t)row0 * ATTNW + col) >> 1] =
            __floats2half2_rn(O[nt][0] * inv0, O[nt][1] * inv0);
        out2[((size_t)(row0 + 8) * ATTNW + col) >> 1] =
            __floats2half2_rn(O[nt][2] * inv1, O[nt][3] * inv1);
    }
}

// ---------------- launch -----------------------------------------------------
extern "C" void kernel_launch(void* const* d_in, const int* in_sizes, int n_in,
                              void* d_out, int out_size) {
    const int* positions = (const int*)d_in[0];
    const float* hidden = (const float*)d_in[1];
    const float* w_qa = (const float*)d_in[2];
    const float* gamma_q = (const float*)d_in[3];
    const float* w_qb = (const float*)d_in[4];
    const float* w_kva = (const float*)d_in[5];
    const float* gamma_kv = (const float*)d_in[6];
    const float* w_kvb = (const float*)d_in[7];
    const float* w_o = (const float*)d_in[8];
    float* out = (float*)d_out;

    __half *hid_h, *wcmbT, *wqbT, *wkvbT, *woT, *cmbh, *qh, *kvuph, *kpeh, *attnh;
    cudaGetSymbolAddress((void**)&hid_h, g_hid_h);
    cudaGetSymbolAddress((void**)&wcmbT, g_wcmbT);
    cudaGetSymbolAddress((void**)&wqbT, g_wqbT);
    cudaGetSymbolAddress((void**)&wkvbT, g_wkvbT);
    cudaGetSymbolAddress((void**)&woT, g_woT);
    cudaGetSymbolAddress((void**)&cmbh, g_cmbh);
    cudaGetSymbolAddress((void**)&qh, g_qh);
    cudaGetSymbolAddress((void**)&kvuph, g_kvuph);
    cudaGetSymbolAddress((void**)&kpeh, g_kpeh);
    cudaGetSymbolAddress((void**)&attnh, g_attnh);

    cudaFuncSetAttribute(gemm_h, cudaFuncAttributeMaxDynamicSharedMemorySize, GSMEM);
    cudaFuncSetAttribute(flash_h, cudaFuncAttributeMaxDynamicSharedMemorySize,
                         FLASH_SMEM);

    const float SCALE_L2E = 0.07216878364870323f * 1.4426950408889634f;
    const int MB = T_TOK / 128;  // 16
    const dim3 tb(32, 8);

    // 1: hidden fp32 -> fp16
    cvt_h_kernel<<<2048, 256>>>(hidden, hid_h, T_TOK * HIDDEN / 4);
    // 2,3: transpose-convert [w_qa | w_kva] -> wcmbT [2112][5120]
    cvtT_kernel<<<dim3(QLORA / 32, HIDDEN / 32), tb>>>(w_qa, wcmbT, HIDDEN, QLORA, 0);
    cvtT_kernel<<<dim3(KV_W / 32, HIDDEN / 32), tb>>>(w_kva, wcmbT, HIDDEN, KV_W, QLORA);
    // 4: w_qb -> wqbT [6144][1536]
    cvtT_kernel<<<dim3(QW / 32, QLORA / 32), tb>>>(w_qb, wqbT, QLORA, QW, 0);
    // 5 (PROFILED): merged down-proj [q_a | kv_c | pe->kpe]   [2048,2112]
    gemm_h<<<dim3((CMBW + 127) / 128, MB), 256, GSMEM>>>(
        hid_h, HIDDEN, wcmbT, HIDDEN, cmbh, CMBW, CMBW, HIDDEN,
        1.f, 2, QLORA + KVLORA, 0, positions, kpeh);
    // 6,7: rmsnorm in place
    rmsnorm_h<<<T_TOK, 256>>>(cmbh, gamma_q, QLORA, CMBW);
    rmsnorm_h<<<T_TOK, 256>>>(cmbh + QLORA, gamma_kv, KVLORA, CMBW);
    // 8: q = (q_c @ w_qb) * scale*log2e, q-RoPE fused          [2048,6144]
    gemm_h<<<dim3(QW / 128, MB), 256, GSMEM>>>(
        cmbh, CMBW, wqbT, QLORA, qh, QW, QW, QLORA,
        SCALE_L2E, 1, 0, 0, positions, kpeh);
    // 9: w_kvb -> wkvbT [8192][512]
    cvtT_kernel<<<dim3(KVUPW / 32, KVLORA / 32), tb>>>(w_kvb, wkvbT, KVLORA, KVUPW, 0);
    // 10: kv_up = kv_c @ w_kvb                                 [2048,8192]
    gemm_h<<<dim3(KVUPW / 128, MB), 256, GSMEM>>>(
        cmbh + QLORA, CMBW, wkvbT, KVLORA, kvuph, KVUPW, KVUPW, KVLORA,
        1.f, 0, 0, 0, positions, kpeh);
    // 11: w_o -> woT [5120][4096]
    cvtT_kernel<<<dim3(HIDDEN / 32, ATTNW / 32), tb>>>(w_o, woT, ATTNW, HIDDEN, 0);
    // 12: attention
    flash_h<<<dim3(T_TOK / 128, NH), 256, FLASH_SMEM>>>(qh, kvuph, kpeh, attnh);
    // 13: out = attn @ w_o (fp32 out)                          [2048,5120]
    gemm_h<<<dim3(HIDDEN / 128, MB), 256, GSMEM>>>(
        attnh, ATTNW, woT, ATTNW, out, HIDDEN, HIDDEN, ATTNW,
        1.f, 0, 0, 1, positions, kpeh);
}

// round 13
// speedup vs baseline: 1.8046x; 1.0922x over previous
#include <cuda_runtime.h>
#include <cuda_fp16.h>
#include <math.h>
#include <stdint.h>

#define T_TOK 2048
#define HIDDEN 5120
#define NH 32
#define DQ 128
#define DR 64
#define DV 128
#define QLORA 1536
#define KVLORA 512
#define KV_W (KVLORA + DR)        // 576
#define QDIM (DQ + DR)            // 192
#define KVUPW (NH * (DQ + DV))    // 8192
#define QW (NH * QDIM)            // 6144
#define ATTNW (NH * DV)           // 4096
#define CMBW (QLORA + KV_W)       // 2112

// ---------------- scratch (device globals; no runtime allocation) ----------
__device__ __half g_hid_h[T_TOK * HIDDEN];
__device__ __half g_wcmbT[CMBW * HIDDEN];    // [2112][5120] K-major
__device__ __half g_wqbT[QW * QLORA];        // [6144][1536]
__device__ __half g_wkvbT[KVUPW * KVLORA];   // [8192][512]
__device__ __half g_woT[HIDDEN * ATTNW];     // [5120][4096]
__device__ __half g_cmbh[T_TOK * CMBW];
__device__ __half g_qh[T_TOK * QW];
__device__ __half g_kvuph[T_TOK * KVUPW];
__device__ __half g_kpeh[T_TOK * DR];
__device__ __half g_attnh[T_TOK * ATTNW];

// ======================= helpers ===========================================
__device__ __forceinline__ uint32_t smem_u32(const void* p) {
    uint32_t a;
    asm("{ .reg .u64 t; cvta.to.shared.u64 t, %1; cvt.u32.u64 %0, t; }"
        : "=r"(a) : "l"(p));
    return a;
}

__device__ __forceinline__ float ex2f(float x) {
    float y;
    asm("ex2.approx.ftz.f32 %0, %1;" : "=f"(y) : "f"(x));
    return y;
}

__device__ __forceinline__ uint32_t ex2h2(uint32_t x) {
    uint32_t y;
    asm("ex2.approx.f16x2 %0, %1;" : "=r"(y) : "r"(x));
    return y;
}

__device__ __forceinline__ void mma_f16(float c[4], const uint32_t a[4],
                                        uint32_t b0, uint32_t b1) {
    asm volatile(
        "mma.sync.aligned.m16n8k16.row.col.f32.f16.f16.f32 "
        "{%0,%1,%2,%3}, {%4,%5,%6,%7}, {%8,%9}, {%0,%1,%2,%3};"
        : "+f"(c[0]), "+f"(c[1]), "+f"(c[2]), "+f"(c[3])
        : "r"(a[0]), "r"(a[1]), "r"(a[2]), "r"(a[3]), "r"(b0), "r"(b1));
}

__device__ __forceinline__ void ldsm4(uint32_t& r0, uint32_t& r1,
                                      uint32_t& r2, uint32_t& r3, uint32_t addr) {
    asm volatile("ldmatrix.sync.aligned.m8n8.x4.shared.b16 {%0,%1,%2,%3}, [%4];"
                 : "=r"(r0), "=r"(r1), "=r"(r2), "=r"(r3) : "r"(addr));
}

__device__ __forceinline__ void ldsm2(uint32_t& r0, uint32_t& r1, uint32_t addr) {
    asm volatile("ldmatrix.sync.aligned.m8n8.x2.shared.b16 {%0,%1}, [%2];"
                 : "=r"(r0), "=r"(r1) : "r"(addr));
}

__device__ __forceinline__ uint32_t h2u(__half2 h) {
    return *reinterpret_cast<uint32_t*>(&h);
}

// ---------------- fp32 -> fp16 conversion kernels --------------------------
__global__ void cvt_h_kernel(const float* __restrict__ in,
                             __half* __restrict__ o, int n4) {
    __half2* o2 = (__half2*)o;
    for (int i = blockIdx.x * 256 + threadIdx.x; i < n4; i += gridDim.x * 256) {
        float4 v = ((const float4*)in)[i];
        o2[2 * i] = __floats2half2_rn(v.x, v.y);
        o2[2 * i + 1] = __floats2half2_rn(v.z, v.w);
    }
}

// transpose + convert: in [Kd][Nd] fp32 -> out rows [orow + n][Kd] fp16
__global__ void cvtT_kernel(const float* __restrict__ in,
                            __half* __restrict__ out,
                            int Kd, int Nd, int orow) {
    __shared__ float t[32][33];
    const int n0 = blockIdx.x * 32, k0 = blockIdx.y * 32;
    const int x = threadIdx.x, y = threadIdx.y;  // (32,8)
#pragma unroll
    for (int j = 0; j < 4; j++)
        t[y + 8 * j][x] = in[(size_t)(k0 + y + 8 * j) * Nd + n0 + x];
    __syncthreads();
#pragma unroll
    for (int j = 0; j < 4; j++)
        out[(size_t)(orow + n0 + y + 8 * j) * Kd + k0 + x] =
            __float2half_rn(t[x][y + 8 * j]);
}

// ---------------- RoPE frequency -------------------------------------------
#define L2T_32 0.41524101186091903f   // log2(10000)/32
__device__ __forceinline__ float rope_freq(int i) {
    return exp2f(-(float)(i & 31) * L2T_32);
}

// ======================= fp16 mma.sync GEMM ================================
// C[M,N] = A[M,K] @ B[K,N]; A fp16 row-major [M][K]; B pre-transposed fp16
// [N][K]. M mult of 128, K mult of 32. CTA 128x128, BK=32, 3-stage cp.async,
// 256 thr (8 warps 4x2, warp tile 32x64, m16n8k16, ldmatrix frag loads).
#define RS 20
#define GSTG (128 * RS * 4)          // 10240 B per operand
#define GSTAGE (2 * GSTG)            // 20480 B per stage
#define GSMEM (3 * GSTAGE)           // 61440 B

__device__ __forceinline__ void g_load(uint32_t sbase, int s,
        const __half* __restrict__ A, int lda,
        const __half* __restrict__ BT, int ldb,
        int brow, int bcol, int N, int k0, int tid) {
    const uint32_t sA = sbase + s * GSTAGE;
    const uint32_t sB = sA + GSTG;
#pragma unroll
    for (int it = 0; it < 2; it++) {
        const int f = it * 256 + tid;
        const int r = f >> 2, c = f & 3;
        const uint32_t dst = sA + (r * RS + c * 4) * 4;
        const __half* src = A + (size_t)(brow + r) * lda + k0 + c * 8;
        asm volatile("cp.async.ca.shared.global [%0], [%1], 16;"
                     :: "r"(dst), "l"(src) : "memory");
    }
#pragma unroll
    for (int it = 0; it < 2; it++) {
        const int f = it * 256 + tid;
        const int r = f >> 2, c = f & 3;
        const uint32_t dst = sB + (r * RS + c * 4) * 4;
        const __half* src = BT + (size_t)(bcol + r) * ldb + k0 + c * 8;
        const int sz = (bcol + r < N) ? 16 : 0;
        asm volatile("cp.async.ca.shared.global [%0], [%1], 16, %2;"
                     :: "r"(dst), "l"(src), "r"(sz) : "memory");
    }
    asm volatile("cp.async.commit_group;" ::: "memory");
}

// mode: 0 plain; 1 q-RoPE ((col%192)>=128 rotated); 2 pe-split (col>=pe0 ->
// kpe). outfp32: C treated as float* (final output), else __half*.
__global__ __launch_bounds__(256, 2) void gemm_h(
        const __half* __restrict__ A, int lda,
        const __half* __restrict__ BT, int ldb,
        void* __restrict__ Cv, int ldc, int N, int K,
        float oscale, int mode, int pe0, int outfp32,
        const int* __restrict__ pos, __half* __restrict__ kpe) {
    extern __shared__ char sm[];
    const uint32_t sbase = smem_u32(sm);
    const int tid = threadIdx.x;
    const int lane = tid & 31;
    const int wid = tid >> 5;
    const int wm = wid >> 1, wn = wid & 1;
    const int brow = blockIdx.y * 128;
    const int bcol = blockIdx.x * 128;
    const int r = lane >> 2, c2 = lane & 3;

    float acc[2][8][4];
#pragma unroll
    for (int mi = 0; mi < 2; mi++)
#pragma unroll
        for (int ni = 0; ni < 8; ni++)
#pragma unroll
            for (int j = 0; j < 4; j++) acc[mi][ni][j] = 0.f;

    // ldmatrix per-lane byte offsets
    const uint32_t aoff = ((wm * 32 + (lane & 7) + 8 * ((lane >> 3) & 1)) * RS
                           + 4 * (lane >> 4)) * 4;
    const uint32_t boff = ((wn * 64 + (lane & 7) + 8 * (lane >> 4)) * RS
                           + 4 * ((lane >> 3) & 1)) * 4;

    const int nch = K / 32;
    g_load(sbase, 0, A, lda, BT, ldb, brow, bcol, N, 0, tid);
    g_load(sbase, 1, A, lda, BT, ldb, brow, bcol, N, 32, tid);

    for (int i = 0; i < nch; i++) {
        const int s = i % 3;
        if (i + 1 < nch) {
            asm volatile("cp.async.wait_group 1;" ::: "memory");
        } else {
            asm volatile("cp.async.wait_group 0;" ::: "memory");
        }
        __syncthreads();

        const uint32_t sAb = sbase + s * GSTAGE;
        const uint32_t sBb = sAb + GSTG;

#pragma unroll
        for (int t = 0; t < 2; t++) {
            uint32_t a[2][4];
            ldsm4(a[0][0], a[0][1], a[0][2], a[0][3], sAb + aoff + t * 32);
            ldsm4(a[1][0], a[1][1], a[1][2], a[1][3],
                  sAb + aoff + 16 * RS * 4 + t * 32);
#pragma unroll
            for (int n2 = 0; n2 < 4; n2++) {
                uint32_t b0, b1, b2, b3;
                ldsm4(b0, b1, b2, b3, sBb + boff + n2 * (16 * RS * 4) + t * 32);
                mma_f16(acc[0][2 * n2], a[0], b0, b1);
                mma_f16(acc[1][2 * n2], a[1], b0, b1);
                mma_f16(acc[0][2 * n2 + 1], a[0], b2, b3);
                mma_f16(acc[1][2 * n2 + 1], a[1], b2, b3);
            }
        }
        if (i + 2 < nch)
            g_load(sbase, (i + 2) % 3, A, lda, BT, ldb, brow, bcol, N,
                   (i + 2) * 32, tid);
    }

    // ---- epilogue ----
    __half* Ch = (__half*)Cv;
    float* Cf = (float*)Cv;
#pragma unroll
    for (int mi = 0; mi < 2; mi++) {
        const int r0 = brow + wm * 32 + mi * 16 + r;
        const int r1 = r0 + 8;
        float fp0 = 0.f, fp1 = 0.f;
        if (mode != 0) { fp0 = (float)pos[r0]; fp1 = (float)pos[r1]; }
#pragma unroll
        for (int ni = 0; ni < 8; ni++) {
            const int col = bcol + wn * 64 + ni * 8 + c2 * 2;
            if (col >= N) continue;
            float x0 = acc[mi][ni][0] * oscale, x1 = acc[mi][ni][1] * oscale;
            float x2 = acc[mi][ni][2] * oscale, x3 = acc[mi][ni][3] * oscale;

            if (mode == 1) {
                const int d = col % QDIM;
                if (d >= DQ) {
                    const int i0 = d - DQ;
                    const float f0 = rope_freq(i0), f1 = rope_freq(i0 + 1);
                    float s0, c0, s1, c1;
                    sincosf(fp0 * f0, &s0, &c0);
                    sincosf(fp0 * f1, &s1, &c1);
                    float nx0 = x0 * c0 - x1 * s0;
                    float nx1 = x1 * c1 + x0 * s1;
                    x0 = nx0; x1 = nx1;
                    sincosf(fp1 * f0, &s0, &c0);
                    sincosf(fp1 * f1, &s1, &c1);
                    float nx2 = x2 * c0 - x3 * s0;
                    float nx3 = x3 * c1 + x2 * s1;
                    x2 = nx2; x3 = nx3;
                }
            } else if (mode == 2 && col >= pe0) {
                const int i0 = col - pe0;
                const float f0 = rope_freq(i0), f1 = rope_freq(i0 + 1);
                float s0, c0, s1, c1;
                sincosf(fp0 * f0, &s0, &c0);
                sincosf(fp0 * f1, &s1, &c1);
                ((__half2*)kpe)[((size_t)r0 * DR + i0) >> 1] =
                    __floats2half2_rn(x0 * c0 - x1 * s0, x1 * c1 + x0 * s1);
                sincosf(fp1 * f0, &s0, &c0);
                sincosf(fp1 * f1, &s1, &c1);
                ((__half2*)kpe)[((size_t)r1 * DR + i0) >> 1] =
                    __floats2half2_rn(x2 * c0 - x3 * s0, x3 * c1 + x2 * s1);
                continue;
            }

            if (outfp32) {
                *(float2*)&Cf[(size_t)r0 * ldc + col] = make_float2(x0, x1);
                *(float2*)&Cf[(size_t)r1 * ldc + col] = make_float2(x2, x3);
            } else {
                ((__half2*)Ch)[((size_t)r0 * ldc + col) >> 1] =
                    __floats2half2_rn(x0, x1);
                ((__half2*)Ch)[((size_t)r1 * ldc + col) >> 1] =
                    __floats2half2_rn(x2, x3);
            }
        }
    }
}

// ---------------- RMSNorm in place on fp16 ----------------------------------
__global__ void rmsnorm_h(__half* __restrict__ x, const float* __restrict__ g,
                          int width, int stride) {
    const int row = blockIdx.x;
    __half2* p = (__half2*)(x + (size_t)row * stride);
    const int tid = threadIdx.x;
    const int w2 = width >> 1;
    float s = 0.f;
    for (int i = tid; i < w2; i += 256) {
        float2 f = __half22float2(p[i]);
        s += f.x * f.x + f.y * f.y;
    }
    __shared__ float red[256];
    red[tid] = s;
    __syncthreads();
    for (int o = 128; o > 0; o >>= 1) {
        if (tid < o) red[tid] += red[tid + o];
        __syncthreads();
    }
    const float inv = rsqrtf(red[0] / (float)width + 1e-6f);
    for (int i = tid; i < w2; i += 256) {
        float2 f = __half22float2(p[i]);
        p[i] = __floats2half2_rn(f.x * inv * g[2 * i], f.y * inv * g[2 * i + 1]);
    }
}

// ================ flash attention, fp16 mma, log2-domain softmax ===========
// grid (16, 32): 128 q rows/CTA, 8 warps (16 rows each), k-tiles of 64.
// Q pre-scaled by (DQ+DR)^-0.5 * log2(e). Ones-column in V computes row sums
// via the PV mma (l tracking folded into O). ldmatrix fragment loads.
#define QS 100   // sQ [128 q][96 u32 data]
#define KS 100   // sK [64 tok][96 u32]
#define VS 36    // sV [136 dv][32 u32]  (V transposed; rows 128..135 = ones/0)
#define PS 36    // sP [128 q][32 u32]
#define FLASH_SMEM ((128 * QS + 64 * KS + 136 * VS + 128 * PS) * 4)  // 114816

__global__ __launch_bounds__(256, 1) void flash_h(
        const __half* __restrict__ q, const __half* __restrict__ kvup,
        const __half* __restrict__ kpe, __half* __restrict__ out) {
    const int ib = blockIdx.x;
    const int h = blockIdx.y;
    const int tid = threadIdx.x;
    const int lane = tid & 31;
    const int wid = tid >> 5;
    const int r = lane >> 2, c2 = lane & 3;

    extern __shared__ uint32_t fs[];
    uint32_t* sQ = fs;                 // 12800 u32
    uint32_t* sK = sQ + 128 * QS;      // 6400
    uint32_t* sV = sK + 64 * KS;       // 4896
    uint32_t* sP = sV + 136 * VS;      // 4608
    const uint32_t sQb = smem_u32(sQ);
    const uint32_t sKb = smem_u32(sK);
    const uint32_t sVb = smem_u32(sV);
    const uint32_t sPb = smem_u32(sP);

    // Q tile: 128 rows x 192 halves (96 u32)
    for (int idx = tid; idx < 128 * 24; idx += 256) {
        const int rr = idx / 24, d4 = idx % 24;
        *(float4*)&sQ[rr * QS + d4 * 4] =
            *(const float4*)(q + (size_t)(ib * 128 + rr) * QW + h * QDIM + d4 * 8);
    }
    // ones rows of V (dv=128 -> 1.0, 129..135 -> 0); written once
    for (int idx = tid; idx < 8 * 32; idx += 256) {
        const int rr = 128 + (idx >> 5), c = idx & 31;
        sV[rr * VS + c] = (rr == 128) ? 0x3C003C00u : 0u;
    }

    // ldmatrix per-lane byte offsets
    const uint32_t qoff = ((wid * 16 + (lane & 7) + 8 * ((lane >> 3) & 1)) * QS
                          + 4 * (lane >> 4)) * 4;
    const uint32_t koff = (((lane & 7) + 8 * (lane >> 4)) * KS
                          + 4 * ((lane >> 3) & 1)) * 4;
    const uint32_t poff = ((wid * 16 + (lane & 7) + 8 * ((lane >> 3) & 1)) * PS
                          + 4 * (lane >> 4)) * 4;
    const uint32_t voff = (((lane & 7) + 8 * (lane >> 4)) * VS
                          + 4 * ((lane >> 3) & 1)) * 4;
    const uint32_t ooff = ((128 + (lane & 7)) * VS + 4 * ((lane >> 3) & 1)) * 4;

    const int qr0 = ib * 128 + wid * 16 + r;
    float m0 = -INFINITY, m1 = -INFINITY;
    float O[16][4], Osum[4];
#pragma unroll
    for (int nt = 0; nt < 16; nt++)
#pragma unroll
        for (int j = 0; j < 4; j++) O[nt][j] = 0.f;
#pragma unroll
    for (int j = 0; j < 4; j++) Osum[j] = 0.f;

    const uint32_t* kvu = (const uint32_t*)kvup;
    const int njb = 2 * ib + 2;
    for (int jb = 0; jb < njb; jb++) {
        __syncthreads();
        // K tile: 64 tok x 192 halves (nope | roped pe)
        for (int idx = tid; idx < 64 * 24; idx += 256) {
            const int rr = idx / 24, d4 = idx % 24;
            const int kt = jb * 64 + rr;
            float4 v;
            if (d4 < 16)
                v = *(const float4*)(kvup + (size_t)kt * KVUPW + h * 256 + d4 * 8);
            else
                v = *(const float4*)(kpe + (size_t)kt * DR + (d4 - 16) * 8);
            *(float4*)&sK[rr * KS + d4 * 4] = v;
        }
        // V tile transposed: [dv 128][tok 64] via byte_perm repack
        for (int idx = tid; idx < 2048; idx += 256) {
            const int dvp = idx & 63, tkp = idx >> 6;
            const size_t base =
                ((size_t)(jb * 64 + 2 * tkp) * KVUPW + h * 256 + 128) >> 1;
            const uint32_t a = kvu[base + dvp];
            const uint32_t b = kvu[base + (KVUPW >> 1) + dvp];
            sV[(2 * dvp) * VS + tkp] = __byte_perm(a, b, 0x5410);
            sV[(2 * dvp + 1) * VS + tkp] = __byte_perm(a, b, 0x7632);
        }
        __syncthreads();

        // ---- S = Q K^T ----
        float S[8][4];
#pragma unroll
        for (int nt = 0; nt < 8; nt++)
#pragma unroll
            for (int j = 0; j < 4; j++) S[nt][j] = 0.f;

#pragma unroll
        for (int ks = 0; ks < 12; ks++) {
            uint32_t a[4];
            ldsm4(a[0], a[1], a[2], a[3], sQb + qoff + ks * 32);
#pragma unroll
            for (int n2 = 0; n2 < 4; n2++) {
                uint32_t b0, b1, b2, b3;
                ldsm4(b0, b1, b2, b3, sKb + koff + n2 * (16 * KS * 4) + ks * 32);
                mma_f16(S[2 * n2], a, b0, b1);
                mma_f16(S[2 * n2 + 1], a, b2, b3);
            }
        }

        // ---- causal mask ----
        if (jb >= 2 * ib) {
#pragma unroll
            for (int nt = 0; nt < 8; nt++) {
                const int kc = jb * 64 + nt * 8 + c2 * 2;
                if (kc > qr0)     S[nt][0] = -1e30f;
                if (kc + 1 > qr0) S[nt][1] = -1e30f;
                if (kc > qr0 + 8)     S[nt][2] = -1e30f;
                if (kc + 1 > qr0 + 8) S[nt][3] = -1e30f;
            }
        }

        // ---- online softmax (log2 domain, f16x2 exp) ----
        float mx0 = -INFINITY, mx1 = -INFINITY;
#pragma unroll
        for (int nt = 0; nt < 8; nt++) {
            mx0 = fmaxf(mx0, fmaxf(S[nt][0], S[nt][1]));
            mx1 = fmaxf(mx1, fmaxf(S[nt][2], S[nt][3]));
        }
        mx0 = fmaxf(mx0, __shfl_xor_sync(0xffffffffu, mx0, 1));
        mx0 = fmaxf(mx0, __shfl_xor_sync(0xffffffffu, mx0, 2));
        mx1 = fmaxf(mx1, __shfl_xor_sync(0xffffffffu, mx1, 1));
        mx1 = fmaxf(mx1, __shfl_xor_sync(0xffffffffu, mx1, 2));
        const float mn0 = fmaxf(m0, mx0), mn1 = fmaxf(m1, mx1);
        const float al0 = ex2f(m0 - mn0), al1 = ex2f(m1 - mn1);
        m0 = mn0; m1 = mn1;
        const int prow = wid * 16 + r;
#pragma unroll
        for (int nt = 0; nt < 8; nt++) {
            sP[prow * PS + nt * 4 + c2] =
                ex2h2(h2u(__floats2half2_rn(S[nt][0] - mn0, S[nt][1] - mn0)));
            sP[(prow + 8) * PS + nt * 4 + c2] =
                ex2h2(h2u(__floats2half2_rn(S[nt][2] - mn1, S[nt][3] - mn1)));
        }
#pragma unroll
        for (int nt = 0; nt < 16; nt++) {
            O[nt][0] *= al0; O[nt][1] *= al0;
            O[nt][2] *= al1; O[nt][3] *= al1;
        }
        Osum[0] *= al0; Osum[1] *= al0;
        Osum[2] *= al1; Osum[3] *= al1;
        __syncwarp();

        // ---- O += P V (ones column accumulates row sums into Osum) ----
#pragma unroll
        for (int kf = 0; kf < 4; kf++) {
            uint32_t a[4];
            ldsm4(a[0], a[1], a[2], a[3], sPb + poff + kf * 32);
#pragma unroll
            for (int n2 = 0; n2 < 8; n2++) {
                uint32_t b0, b1, b2, b3;
                ldsm4(b0, b1, b2, b3, sVb + voff + n2 * (16 * VS * 4) + kf * 32);
                mma_f16(O[2 * n2], a, b0, b1);
                mma_f16(O[2 * n2 + 1], a, b2, b3);
            }
            uint32_t o0, o1;
            ldsm2(o0, o1, sVb + ooff + kf * 32);
            mma_f16(Osum, a, o0, o1);
        }
    }

    // ---- epilogue: extract row sums, normalize, store fp16 ----
    const float s0 = __shfl_sync(0xffffffffu, Osum[0], lane & ~3);
    const float s1 = __shfl_sync(0xffffffffu, Osum[2], lane & ~3);
    const float inv0 = 1.f / s0, inv1 = 1.f / s1;
    const int row0 = ib * 128 + wid * 16 + r;
    __half2* out2 = (__half2*)out;
#pragma unroll
    for (int nt = 0; nt < 16; nt++) {
        const int col = h * DV + nt * 8 + c2 * 2;
        out2[((size_t)row0 * ATTNW + col) >> 1] =
            __floats2half2_rn(O[nt][0] * inv0, O[nt][1] * inv0);
        out2[((size_t)(row0 + 8) * ATTNW + col) >> 1] =
            __floats2half2_rn(O[nt][2] * inv1, O[nt][3] * inv1);
    }
}

// ---------------- launch -----------------------------------------------------
extern "C" void kernel_launch(void* const* d_in, const int* in_sizes, int n_in,
                              void* d_out, int out_size) {
    const int* positions = (const int*)d_in[0];
    const float* hidden = (const float*)d_in[1];
    const float* w_qa = (const float*)d_in[2];
    const float* gamma_q = (const float*)d_in[3];
    const float* w_qb = (const float*)d_in[4];
    const float* w_kva = (const float*)d_in[5];
    const float* gamma_kv = (const float*)d_in[6];
    const float* w_kvb = (const float*)d_in[7];
    const float* w_o = (const float*)d_in[8];
    float* out = (float*)d_out;

    __half *hid_h, *wcmbT, *wqbT, *wkvbT, *woT, *cmbh, *qh, *kvuph, *kpeh, *attnh;
    cudaGetSymbolAddress((void**)&hid_h, g_hid_h);
    cudaGetSymbolAddress((void**)&wcmbT, g_wcmbT);
    cudaGetSymbolAddress((void**)&wqbT, g_wqbT);
    cudaGetSymbolAddress((void**)&wkvbT, g_wkvbT);
    cudaGetSymbolAddress((void**)&woT, g_woT);
    cudaGetSymbolAddress((void**)&cmbh, g_cmbh);
    cudaGetSymbolAddress((void**)&qh, g_qh);
    cudaGetSymbolAddress((void**)&kvuph, g_kvuph);
    cudaGetSymbolAddress((void**)&kpeh, g_kpeh);
    cudaGetSymbolAddress((void**)&attnh, g_attnh);

    cudaFuncSetAttribute(gemm_h, cudaFuncAttributeMaxDynamicSharedMemorySize, GSMEM);
    cudaFuncSetAttribute(flash_h, cudaFuncAttributeMaxDynamicSharedMemorySize,
                         FLASH_SMEM);

    const float SCALE_L2E = 0.07216878364870323f * 1.4426950408889634f;
    const int MB = T_TOK / 128;  // 16
    const dim3 tb(32, 8);

    // 1: hidden fp32 -> fp16
    cvt_h_kernel<<<2048, 256>>>(hidden, hid_h, T_TOK * HIDDEN / 4);
    // 2,3: transpose-convert [w_qa | w_kva] -> wcmbT [2112][5120]
    cvtT_kernel<<<dim3(QLORA / 32, HIDDEN / 32), tb>>>(w_qa, wcmbT, HIDDEN, QLORA, 0);
    cvtT_kernel<<<dim3(KV_W / 32, HIDDEN / 32), tb>>>(w_kva, wcmbT, HIDDEN, KV_W, QLORA);
    // 4: merged down-proj [q_a | kv_c | pe->kpe]   [2048,2112]
    gemm_h<<<dim3((CMBW + 127) / 128, MB), 256, GSMEM>>>(
        hid_h, HIDDEN, wcmbT, HIDDEN, cmbh, CMBW, CMBW, HIDDEN,
        1.f, 2, QLORA + KVLORA, 0, positions, kpeh);
    // 5: w_qb -> wqbT [6144][1536]
    cvtT_kernel<<<dim3(QW / 32, QLORA / 32), tb>>>(w_qb, wqbT, QLORA, QW, 0);
    // 6,7: rmsnorm in place
    rmsnorm_h<<<T_TOK, 256>>>(cmbh, gamma_q, QLORA, CMBW);
    rmsnorm_h<<<T_TOK, 256>>>(cmbh + QLORA, gamma_kv, KVLORA, CMBW);
    // 8: q = (q_c @ w_qb) * scale*log2e, q-RoPE fused          [2048,6144]
    gemm_h<<<dim3(QW / 128, MB), 256, GSMEM>>>(
        cmbh, CMBW, wqbT, QLORA, qh, QW, QW, QLORA,
        SCALE_L2E, 1, 0, 0, positions, kpeh);
    // 9: w_kvb -> wkvbT [8192][512]
    cvtT_kernel<<<dim3(KVUPW / 32, KVLORA / 32), tb>>>(w_kvb, wkvbT, KVLORA, KVUPW, 0);
    // 10: kv_up = kv_c @ w_kvb                                 [2048,8192]
    gemm_h<<<dim3(KVUPW / 128, MB), 256, GSMEM>>>(
        cmbh + QLORA, CMBW, wkvbT, KVLORA, kvuph, KVUPW, KVUPW, KVLORA,
        1.f, 0, 0, 0, positions, kpeh);
    // 11: w_o -> woT [5120][4096]
    cvtT_kernel<<<dim3(HIDDEN / 32, ATTNW / 32), tb>>>(w_o, woT, ATTNW, HIDDEN, 0);
    // 12: attention
    flash_h<<<dim3(T_TOK / 128, NH), 256, FLASH_SMEM>>>(qh, kvuph, kpeh, attnh);
    // 13: out = attn @ w_o (fp32 out)                          [2048,5120]
    gemm_h<<<dim3(HIDDEN / 128, MB), 256, GSMEM>>>(
        attnh, ATTNW, woT, ATTNW, out, HIDDEN, HIDDEN, ATTNW,
        1.f, 0, 0, 1, positions, kpeh);
}